// round 6
// baseline (speedup 1.0000x reference)
#include <cuda_runtime.h>
#include <stdint.h>
#include <math.h>

#define B_TOTAL   262144
#define IN_DIM    73
#define HID       256
#define PI_F      3.14159265358979323846f
#define NORM_R    (500.0f/150000.0f)

// Packed weight region offsets (floats) inside g_Wg (k-stream layout per row)
#define WG_R      0           // [256][336]  r gate, [W_ih | pad | W_hh]
#define WG_Z      86016       // [256][336]  z gate
#define WG_GIN    172032      // [256][80]   gi_n
#define WG_GHN    192512      // [256][256]  gh_n
#define WG_TOTAL  258048

// ---------------- device scratch ----------------
__device__ __align__(16) float g_Arnn [(size_t)B_TOTAL * 80];     // k-stream (tigStride 20), tf32
__device__ __align__(16) float g_innov[(size_t)B_TOTAL * 27];     // exact fp32
__device__ __align__(16) float g_xm   [(size_t)B_TOTAL * 6];      // exact fp32
__device__ __align__(16) float g_Wg   [WG_TOTAL];
__device__ __align__(16) float g_bias [1024];                     // br, bz, bin, bhn
__device__ __align__(16) float g_W1p  [256 * 256];                // tigStride 64
__device__ __align__(16) float g_W2p  [128 * 256];                // tigStride 64
__device__ __align__(16) float g_W3p  [192 * 128];                // tigStride 32, rows >=162 zero

// ---------------- helpers ----------------
// k-stream position: lane tig=(k&3) owns pair {k8+tig, k8+tig+4}; pairs contiguous across ksteps
__device__ __host__ __forceinline__ int pstr(int k, int tigStride) {
    return (k & 3) * tigStride + ((k >> 3) << 1) + ((k >> 2) & 1);
}
__device__ __forceinline__ float tf32r(float x) {
    uint32_t r;
    asm("cvt.rna.tf32.f32 %0, %1;" : "=r"(r) : "f"(x));
    return __uint_as_float(r);
}
__device__ __forceinline__ void mma8s(float* c, uint32_t a0, uint32_t a1, uint32_t a2,
                                      uint32_t a3, uint32_t b0, uint32_t b1) {
    asm volatile(
        "mma.sync.aligned.m16n8k8.row.col.f32.tf32.tf32.f32 "
        "{%0,%1,%2,%3}, {%4,%5,%6,%7}, {%8,%9}, {%0,%1,%2,%3};"
        : "+f"(c[0]), "+f"(c[1]), "+f"(c[2]), "+f"(c[3])
        : "r"(a0), "r"(a1), "r"(a2), "r"(a3), "r"(b0), "r"(b1));
}
// one uint4 pair = 2 ksteps
__device__ __forceinline__ void mma2(float* c, uint4 aL, uint4 aH, uint4 b) {
    mma8s(c, aL.x, aH.x, aL.y, aH.y, b.x, b.y);
    mma8s(c, aL.z, aH.z, aL.w, aH.w, b.z, b.w);
}
__device__ __forceinline__ float sigm(float x) { return 1.0f / (1.0f + expf(-x)); }

// ================= K0: pack weights (k-stream) =================
__global__ void pack_kernel(const float* __restrict__ W_ih, const float* __restrict__ W_hh,
                            const float* __restrict__ b_ih, const float* __restrict__ b_hh,
                            const float* __restrict__ W1, const float* __restrict__ W2,
                            const float* __restrict__ W3) {
    int i = blockIdx.x * blockDim.x + threadIdx.x;
    if (i < 2 * 256 * 336) {                       // r / z merged gates, K=336 [ih(73)|pad|hh(256)]
        int g = i / (256 * 336);
        int j = (i / 336) % 256, k = i % 336;
        int row = g * 256 + j;
        float v = 0.0f;
        if (k < IN_DIM)    v = W_ih[(size_t)row * IN_DIM + k];
        else if (k >= 80)  v = W_hh[(size_t)row * HID + (k - 80)];
        g_Wg[(g ? WG_Z : WG_R) + j * 336 + pstr(k, 84)] = tf32r(v);
        return;
    }
    i -= 2 * 256 * 336;
    if (i < 256 * 80) {                            // gi_n, K=80
        int j = i / 80, k = i % 80;
        float v = (k < IN_DIM) ? W_ih[(size_t)(512 + j) * IN_DIM + k] : 0.0f;
        g_Wg[WG_GIN + j * 80 + pstr(k, 20)] = tf32r(v);
        return;
    }
    i -= 256 * 80;
    if (i < 256 * 256) {                           // gh_n, K=256
        int j = i / 256, k = i % 256;
        g_Wg[WG_GHN + j * 256 + pstr(k, 64)] = tf32r(W_hh[(size_t)(512 + j) * HID + k]);
        return;
    }
    i -= 256 * 256;
    if (i < 1024) {
        int j = i & 255, t = i >> 8;
        float v;
        if (t == 0)      v = b_ih[j]       + b_hh[j];
        else if (t == 1) v = b_ih[256 + j] + b_hh[256 + j];
        else if (t == 2) v = b_ih[512 + j];
        else             v = b_hh[512 + j];
        g_bias[i] = v;
        return;
    }
    i -= 1024;
    if (i < 256 * 256) {
        int n = i >> 8, k = i & 255;
        g_W1p[n * 256 + pstr(k, 64)] = tf32r(W1[i]);
        return;
    }
    i -= 256 * 256;
    if (i < 128 * 256) {
        int n = i >> 8, k = i & 255;
        g_W2p[n * 256 + pstr(k, 64)] = tf32r(W2[i]);
        return;
    }
    i -= 128 * 256;
    if (i < 192 * 128) {
        int n = i >> 7, k = i & 127;
        g_W3p[n * 128 + pstr(k, 32)] = (n < 162) ? tf32r(W3[n * 128 + k]) : 0.0f;
    }
}
#define PACK_TOTAL (2*256*336 + 256*80 + 256*256 + 1024 + 256*256 + 128*256 + 192*128)

// ================= K1: per-row prep =================
__global__ __launch_bounds__(256)
void prep_kernel(const float* __restrict__ meas, const float* __restrict__ mask,
                 const float* __restrict__ dt,   const float* __restrict__ baselines,
                 const float* __restrict__ x_prev) {
    size_t r = (size_t)blockIdx.x * blockDim.x + threadIdx.x;
    if (r >= B_TOTAL) return;
    float dtv = dt[r];
    float xp[6], bl[12];
#pragma unroll
    for (int i = 0; i < 6; i++)  xp[i] = x_prev[r * 6 + i];
#pragma unroll
    for (int i = 0; i < 12; i++) bl[i] = baselines[r * 12 + i];
    float ds = dtv * NORM_R;
    float xm[6];
    xm[0] = fmaf(ds, xp[1], xp[0]); xm[1] = xp[1];
    xm[2] = fmaf(ds, xp[3], xp[2]); xm[3] = xp[3];
    xm[4] = fmaf(ds, xp[5], xp[4]); xm[5] = xp[5];
#pragma unroll
    for (int i = 0; i < 6; i++) g_xm[r * 6 + i] = xm[i];

    float yp[27];
#pragma unroll
    for (int p = 0; p < 3; p++) {
        float x0 = xm[0], x2 = xm[2], x4 = xm[4];
        if (p == 1) { x0 -= bl[0]; x2 -= bl[2]; x4 -= bl[4]; }
        if (p == 2) { x0 -= bl[6]; x2 -= bl[8]; x4 -= bl[10]; }
        float rxy = sqrtf(x0 * x0 + x2 * x2 + 1e-9f);
        float az  = atan2f(x2, x0) * (1.0f / PI_F);
        float el  = atan2f(x4, rxy) * (1.0f / PI_F);
        float rr  = sqrtf(x0 * x0 + x2 * x2 + x4 * x4 + 1e-9f);
        yp[p*9+0] = az; yp[p*9+1] = el; yp[p*9+2] = rr;
        yp[p*9+3] = az; yp[p*9+4] = el; yp[p*9+5] = 0.0f;
        yp[p*9+6] = az; yp[p*9+7] = 0.0f; yp[p*9+8] = 0.0f;
    }
    float* A = g_Arnn + r * 80;                    // k-stream, tigStride 20
#pragma unroll
    for (int m = 0; m < 27; m++) {
        float mv = meas[r * 27 + m];
        float mk = mask[r * 27 + m];
        float in = mv - yp[m];
        int mm = m % 9;
        bool ang = (mm == 0) | (mm == 1) | (mm == 3) | (mm == 4) | (mm == 6);
        if (ang) in = in - 2.0f * rintf(in * 0.5f);
        in *= mk;
        g_innov[r * 27 + m] = in;
        A[pstr(m, 20)]      = tf32r(in);
        A[pstr(27 + m, 20)] = tf32r(mk);
    }
    A[pstr(54, 20)] = tf32r(dtv);
#pragma unroll
    for (int i = 0; i < 6; i++)  A[pstr(55 + i, 20)] = tf32r(xm[i]);
#pragma unroll
    for (int i = 0; i < 12; i++) A[pstr(61 + i, 20)] = tf32r(bl[i]);
#pragma unroll
    for (int i = 73; i < 80; i++) A[pstr(i, 20)] = 0.0f;
}

// ================= K2: GRU (M=128/CTA) =================
// A tile: K=336 stream, tigStride 84, row stride GS=336 (84 chunks == 4 mod 8: conflict-free)
#define GS 336
#define G_SMEM ((128 * GS + 1024) * 4)

__global__ __launch_bounds__(256, 1)
void gru_kernel(const float* __restrict__ hx, float* __restrict__ out_h) {
    extern __shared__ float sm[];
    float* sA    = sm;                              // [128][336]
    float* sBias = sm + 128 * GS;
    const int tid = threadIdx.x, lane = tid & 31, wid = tid >> 5;
    const int wm = wid & 3, wn = wid >> 2;
    const int r0 = blockIdx.x * 128;

    // stage rnn part: g_Arnn row is [tig][5 x uint4] -> sA tig segments (ksteps 0..9)
    for (int t = tid; t < 128 * 20; t += 256) {
        int row = t / 20, c = t % 20;
        int tig = c / 5, ks2 = c % 5;
        float4 v = *(const float4*)(g_Arnn + (size_t)(r0 + row) * 80 + c * 4);
        *(float4*)(sA + row * GS + tig * 84 + ks2 * 4) = v;
    }
    // stage hx: logical k -> stream pos, A kstep = 10 + (k>>3)
    for (int t = tid; t < 128 * 64; t += 256) {
        int row = t >> 6, kq = (t & 63) << 2;
        float4 v = *(const float4*)(hx + (size_t)(r0 + row) * HID + kq);
        int base = row * GS + ((10 + (kq >> 3)) << 1) + ((kq >> 2) & 1);
        sA[base]       = tf32r(v.x);
        sA[base +  84] = tf32r(v.y);
        sA[base + 168] = tf32r(v.z);
        sA[base + 252] = tf32r(v.w);
    }
    for (int t = tid; t < 1024; t += 256) sBias[t] = g_bias[t];
    __syncthreads();

    const int tig   = lane & 3;
    const int rowA0 = wm * 32 + (lane >> 2);

    for (int pass = 0; pass < 4; pass++) {
        const int jb = pass * 64 + wn * 32;
        float Cr[2][4][4], Cz[2][4][4], Cn[2][4][4], Ch[2][4][4];
#pragma unroll
        for (int mt = 0; mt < 2; mt++)
#pragma unroll
            for (int nt = 0; nt < 4; nt++)
#pragma unroll
                for (int e = 0; e < 4; e++) {
                    Cr[mt][nt][e] = 0.f; Cz[mt][nt][e] = 0.f;
                    Cn[mt][nt][e] = 0.f; Ch[mt][nt][e] = 0.f;
                }

        const int nrow = jb + (lane >> 2);
        const float* BrP = g_Wg + WG_R   + (size_t)nrow * 336 + tig * 84;
        const float* BzP = g_Wg + WG_Z   + (size_t)nrow * 336 + tig * 84;
        const float* BiP = g_Wg + WG_GIN + (size_t)nrow * 80  + tig * 20;
        const float* BhP = g_Wg + WG_GHN + (size_t)nrow * 256 + tig * 64;

        // ---- r & z : K=336, 21 uint4 steps ----
        for (int jj = 0; jj < 21; jj++) {
            uint4 br[4], bz[4];
#pragma unroll
            for (int nt = 0; nt < 4; nt++) {
                br[nt] = *(const uint4*)(BrP + nt * (8 * 336) + jj * 4);
                bz[nt] = *(const uint4*)(BzP + nt * (8 * 336) + jj * 4);
            }
            uint4 aL[2], aH[2];
#pragma unroll
            for (int mt = 0; mt < 2; mt++) {
                const float* ap = sA + (rowA0 + mt * 16) * GS + tig * 84 + jj * 4;
                aL[mt] = *(const uint4*)ap;
                aH[mt] = *(const uint4*)(ap + 8 * GS);
            }
#pragma unroll
            for (int nt = 0; nt < 4; nt++)
#pragma unroll
                for (int mt = 0; mt < 2; mt++) {
                    mma2(Cr[mt][nt], aL[mt], aH[mt], br[nt]);
                    mma2(Cz[mt][nt], aL[mt], aH[mt], bz[nt]);
                }
        }
        // ---- gi_n : K=80, ksteps 0..9 (A stream offset 0), 5 uint4 steps ----
        for (int jj = 0; jj < 5; jj++) {
            uint4 bi[4];
#pragma unroll
            for (int nt = 0; nt < 4; nt++)
                bi[nt] = *(const uint4*)(BiP + nt * (8 * 80) + jj * 4);
            uint4 aL[2], aH[2];
#pragma unroll
            for (int mt = 0; mt < 2; mt++) {
                const float* ap = sA + (rowA0 + mt * 16) * GS + tig * 84 + jj * 4;
                aL[mt] = *(const uint4*)ap;
                aH[mt] = *(const uint4*)(ap + 8 * GS);
            }
#pragma unroll
            for (int nt = 0; nt < 4; nt++)
#pragma unroll
                for (int mt = 0; mt < 2; mt++)
                    mma2(Cn[mt][nt], aL[mt], aH[mt], bi[nt]);
        }
        // ---- gh_n : K=256, A ksteps 10..41 (stream offset +20), 16 uint4 steps ----
        for (int jj = 0; jj < 16; jj++) {
            uint4 bh[4];
#pragma unroll
            for (int nt = 0; nt < 4; nt++)
                bh[nt] = *(const uint4*)(BhP + nt * (8 * 256) + jj * 4);
            uint4 aL[2], aH[2];
#pragma unroll
            for (int mt = 0; mt < 2; mt++) {
                const float* ap = sA + (rowA0 + mt * 16) * GS + tig * 84 + 20 + jj * 4;
                aL[mt] = *(const uint4*)ap;
                aH[mt] = *(const uint4*)(ap + 8 * GS);
            }
#pragma unroll
            for (int nt = 0; nt < 4; nt++)
#pragma unroll
                for (int mt = 0; mt < 2; mt++)
                    mma2(Ch[mt][nt], aL[mt], aH[mt], bh[nt]);
        }
        // ---- epilogue ----
#pragma unroll
        for (int mt = 0; mt < 2; mt++)
#pragma unroll
            for (int nt = 0; nt < 4; nt++)
#pragma unroll
                for (int half = 0; half < 2; half++) {
                    const int row = rowA0 + mt * 16 + half * 8;
                    const int jc  = jb + nt * 8 + (tig << 1);
                    float h2[2];
#pragma unroll
                    for (int e = 0; e < 2; e++) {
                        const int j = jc + e;
                        const int idx = half * 2 + e;
                        float rg = sigm(Cr[mt][nt][idx] + sBias[j]);
                        float zg = sigm(Cz[mt][nt][idx] + sBias[256 + j]);
                        float nn = tanhf(Cn[mt][nt][idx] + sBias[512 + j]
                                         + rg * (Ch[mt][nt][idx] + sBias[768 + j]));
                        float hxv = sA[row * GS + (j & 3) * 84
                                       + ((10 + (j >> 3)) << 1) + ((j >> 2) & 1)];
                        h2[e] = (1.0f - zg) * nn + zg * hxv;
                    }
                    *(float2*)(out_h + (size_t)(r0 + row) * HID + jc) = make_float2(h2[0], h2[1]);
                }
    }
}

// ================= K3: LN + MLP + gain head (M=64/CTA) =================
// S1=272 (68 chunks == 4 mod 8, tig stride 68 = 17 chunks == 1): conflict-free
// S3=144 (36 chunks == 4 mod 8, tig stride 36 = 9 chunks == 1): conflict-free
#define S1 272
#define S3 144
#define SKV 200
#define OFF_A2  (64 * S1)
#define OFF_A3  (OFF_A2 + 64 * S1)
#define OFF_INN (OFF_A3 + 64 * S3)
#define M_SMEM  ((OFF_INN + 64 * 28) * 4)

__global__ __launch_bounds__(256, 1)
void mlp_kernel(const float* __restrict__ h_in,
                const float* __restrict__ ln_g, const float* __restrict__ ln_b,
                const float* __restrict__ b1, const float* __restrict__ b2,
                const float* __restrict__ b3, float* __restrict__ out_x) {
    extern __shared__ float sm[];
    float* sA1  = sm;                 // [64][272] h_ln, later reused as kv [64][SKV]
    float* sA2  = sm + OFF_A2;        // [64][272] f1
    float* sA3  = sm + OFF_A3;        // [64][144] f2
    float* sInn = sm + OFF_INN;       // [64][28]
    const int tid = threadIdx.x, lane = tid & 31, wid = tid >> 5;
    const int wm = wid & 3, wn = wid >> 2;
    const int r0 = blockIdx.x * 64;

    // stage h (k-stream, tigStride 68)
    for (int t = tid; t < 64 * 64; t += 256) {
        int row = t >> 6, kq = (t & 63) << 2;
        float4 v = *(const float4*)(h_in + (size_t)(r0 + row) * HID + kq);
        int base = row * S1 + ((kq >> 3) << 1) + ((kq >> 2) & 1);
        sA1[base]       = v.x;
        sA1[base +  68] = v.y;
        sA1[base + 136] = v.z;
        sA1[base + 204] = v.w;
    }
    for (int t = tid; t < 64 * 27; t += 256) {
        int row = t / 27, m = t % 27;
        sInn[row * 28 + m] = g_innov[(size_t)(r0 + row) * 27 + m];
    }
    __syncthreads();

    // LayerNorm: thread (row, q) owns tig segment q (contiguous 64 floats)
    {
        const int row = tid >> 2, q = tid & 3;
        float* seg = sA1 + row * S1 + q * 68;
        float s = 0.f, sq = 0.f;
        for (int i = 0; i < 64; i++) {
            float v = seg[i];
            s += v; sq = fmaf(v, v, sq);
        }
        s  += __shfl_xor_sync(0xffffffffu, s, 1);  sq += __shfl_xor_sync(0xffffffffu, sq, 1);
        s  += __shfl_xor_sync(0xffffffffu, s, 2);  sq += __shfl_xor_sync(0xffffffffu, sq, 2);
        float mu = s * (1.0f / 256.0f);
        float var = sq * (1.0f / 256.0f) - mu * mu;
        float rs = rsqrtf(var + 1e-5f);
        for (int i = 0; i < 64; i++) {
            int k = ((i >> 1) << 3) + ((i & 1) << 2) + q;  // logical k of stream pos i
            seg[i] = tf32r((seg[i] - mu) * rs * __ldg(ln_g + k) + __ldg(ln_b + k));
        }
    }
    __syncthreads();

    const int tig   = lane & 3;
    const int rowA0 = wm * 16 + (lane >> 2);

    // ---- MLP1: N=256 (4 passes), K=256 (16 uint4 steps), A=sA1 -> f1 in sA2 ----
    for (int p = 0; p < 4; p++) {
        const int nb = p * 64 + wn * 32;
        float C[4][4];
#pragma unroll
        for (int nt = 0; nt < 4; nt++)
#pragma unroll
            for (int e = 0; e < 4; e++) C[nt][e] = 0.f;
        const float* BP = g_W1p + (size_t)(nb + (lane >> 2)) * 256 + tig * 64;
        for (int jj = 0; jj < 16; jj++) {
            uint4 b[4];
#pragma unroll
            for (int nt = 0; nt < 4; nt++) b[nt] = *(const uint4*)(BP + nt * (8 * 256) + jj * 4);
            const float* ap = sA1 + rowA0 * S1 + tig * 68 + jj * 4;
            uint4 aL = *(const uint4*)ap, aH = *(const uint4*)(ap + 8 * S1);
#pragma unroll
            for (int nt = 0; nt < 4; nt++) mma2(C[nt], aL, aH, b[nt]);
        }
#pragma unroll
        for (int nt = 0; nt < 4; nt++)
#pragma unroll
            for (int half = 0; half < 2; half++) {
                const int row = rowA0 + half * 8;
                const int j0  = nb + nt * 8 + (tig << 1);
#pragma unroll
                for (int e = 0; e < 2; e++) {
                    int j = j0 + e;
                    float f = fmaxf(C[nt][half * 2 + e] + __ldg(b1 + j), 0.0f);
                    sA2[row * S1 + pstr(j, 68)] = tf32r(f);
                }
            }
    }
    __syncthreads();

    // ---- MLP2: N=128 (2 passes), K=256, A=sA2 -> f2 in sA3 ----
    for (int p = 0; p < 2; p++) {
        const int nb = p * 64 + wn * 32;
        float C[4][4];
#pragma unroll
        for (int nt = 0; nt < 4; nt++)
#pragma unroll
            for (int e = 0; e < 4; e++) C[nt][e] = 0.f;
        const float* BP = g_W2p + (size_t)(nb + (lane >> 2)) * 256 + tig * 64;
        for (int jj = 0; jj < 16; jj++) {
            uint4 b[4];
#pragma unroll
            for (int nt = 0; nt < 4; nt++) b[nt] = *(const uint4*)(BP + nt * (8 * 256) + jj * 4);
            const float* ap = sA2 + rowA0 * S1 + tig * 68 + jj * 4;
            uint4 aL = *(const uint4*)ap, aH = *(const uint4*)(ap + 8 * S1);
#pragma unroll
            for (int nt = 0; nt < 4; nt++) mma2(C[nt], aL, aH, b[nt]);
        }
#pragma unroll
        for (int nt = 0; nt < 4; nt++)
#pragma unroll
            for (int half = 0; half < 2; half++) {
                const int row = rowA0 + half * 8;
                const int j0  = nb + nt * 8 + (tig << 1);
#pragma unroll
                for (int e = 0; e < 2; e++) {
                    int j = j0 + e;
                    float f = fmaxf(C[nt][half * 2 + e] + __ldg(b2 + j), 0.0f);
                    sA3[row * S3 + pstr(j, 36)] = tf32r(f);
                }
            }
    }
    __syncthreads();

    // ---- MLP3: N=192 (3 passes), K=128 (8 uint4 steps), A=sA3 -> kv in sA1 ----
    for (int p = 0; p < 3; p++) {
        const int nb = p * 64 + wn * 32;
        float C[4][4];
#pragma unroll
        for (int nt = 0; nt < 4; nt++)
#pragma unroll
            for (int e = 0; e < 4; e++) C[nt][e] = 0.f;
        const float* BP = g_W3p + (size_t)(nb + (lane >> 2)) * 128 + tig * 32;
        for (int jj = 0; jj < 8; jj++) {
            uint4 b[4];
#pragma unroll
            for (int nt = 0; nt < 4; nt++) b[nt] = *(const uint4*)(BP + nt * (8 * 128) + jj * 4);
            const float* ap = sA3 + rowA0 * S3 + tig * 36 + jj * 4;
            uint4 aL = *(const uint4*)ap, aH = *(const uint4*)(ap + 8 * S3);
#pragma unroll
            for (int nt = 0; nt < 4; nt++) mma2(C[nt], aL, aH, b[nt]);
        }
#pragma unroll
        for (int nt = 0; nt < 4; nt++)
#pragma unroll
            for (int half = 0; half < 2; half++) {
                const int row = rowA0 + half * 8;
                const int j0  = nb + nt * 8 + (tig << 1);
#pragma unroll
                for (int e = 0; e < 2; e++) {
                    int j = j0 + e;
                    if (j < 162) {
                        float kv = C[nt][half * 2 + e] + __ldg(b3 + j);
                        sA1[row * SKV + j] = fminf(fmaxf(kv, -3.0f), 3.0f);
                    }
                }
            }
    }
    __syncthreads();

    // ---- correction + clamp ----
    for (int t = tid; t < 384; t += 256) {
        const int row = t & 63, s = t >> 6;
        float corr = 0.f;
#pragma unroll
        for (int m = 0; m < 27; m++)
            corr = fmaf(sA1[row * SKV + s * 27 + m], sInn[row * 28 + m], corr);
        float xmv = g_xm[(size_t)(r0 + row) * 6 + s];
        out_x[(size_t)(r0 + row) * 6 + s] = fminf(fmaxf(xmv + corr, -5.0f), 5.0f);
    }
}

// ================= launch =================
extern "C" void kernel_launch(void* const* d_in, const int* in_sizes, int n_in,
                              void* d_out, int out_size)
{
    (void)in_sizes; (void)n_in; (void)out_size;
    const float* meas      = (const float*)d_in[0];
    const float* mask      = (const float*)d_in[1];
    const float* dtv       = (const float*)d_in[2];
    const float* baselines = (const float*)d_in[3];
    const float* x_prev    = (const float*)d_in[4];
    const float* hx        = (const float*)d_in[5];
    const float* W_ih      = (const float*)d_in[6];
    const float* W_hh      = (const float*)d_in[7];
    const float* b_ih      = (const float*)d_in[8];
    const float* b_hh      = (const float*)d_in[9];
    const float* ln_g      = (const float*)d_in[10];
    const float* ln_b      = (const float*)d_in[11];
    const float* W1        = (const float*)d_in[12];
    const float* b1        = (const float*)d_in[13];
    const float* W2        = (const float*)d_in[14];
    const float* b2        = (const float*)d_in[15];
    const float* W3        = (const float*)d_in[16];
    const float* b3        = (const float*)d_in[17];

    float* out   = (float*)d_out;
    float* out_x = out;                            // [B, 6]
    float* out_h = out + (size_t)B_TOTAL * 6;      // [B, 256]

    pack_kernel<<<(PACK_TOTAL + 255) / 256, 256>>>(W_ih, W_hh, b_ih, b_hh, W1, W2, W3);
    prep_kernel<<<B_TOTAL / 256, 256>>>(meas, mask, dtv, baselines, x_prev);

    cudaFuncSetAttribute(gru_kernel, cudaFuncAttributeMaxDynamicSharedMemorySize, G_SMEM);
    gru_kernel<<<B_TOTAL / 128, 256, G_SMEM>>>(hx, out_h);

    cudaFuncSetAttribute(mlp_kernel, cudaFuncAttributeMaxDynamicSharedMemorySize, M_SMEM);
    mlp_kernel<<<B_TOTAL / 64, 256, M_SMEM>>>(out_h, ln_g, ln_b, b1, b2, b3, out_x);
}

// round 7
// speedup vs baseline: 1.7974x; 1.7974x over previous
#include <cuda_runtime.h>
#include <stdint.h>
#include <math.h>

#define B_TOTAL   262144
#define IN_DIM    73
#define KRNN      80
#define HID       256
#define PI_F      3.14159265358979323846f
#define NORM_R    (500.0f/150000.0f)

// Fragment-order packed weights: [ntile][ks2][128] with pos = lane*4 + e4
// value(lane,e4) = W[n = ntile*8 + lane/4][k = (2*ks2 + (e4>>1))*8 + lane%4 + 4*(e4&1)]
#define WG_R      0            // 32 ntiles x 21 ks2 x 128 = 86016   (K=336: [ih|pad|hh])
#define WG_Z      86016        // 32 x 21 x 128
#define WG_GIN    172032       // 32 x 5  x 128 = 20480              (K=80)
#define WG_GHN    192512       // 32 x 16 x 128 = 65536              (K=256)
#define WG_TOTAL  258048

// ---------------- device scratch ----------------
__device__ __align__(16) float g_Arnn [(size_t)B_TOTAL * KRNN];   // pair-permuted, tf32
__device__ __align__(16) float g_innov[(size_t)B_TOTAL * 27];
__device__ __align__(16) float g_xm   [(size_t)B_TOTAL * 6];
__device__ __align__(16) float g_Wg   [WG_TOTAL];
__device__ __align__(16) float g_bias [1024];
__device__ __align__(16) float g_W1p  [32 * 16 * 128];            // 65536
__device__ __align__(16) float g_W2p  [16 * 16 * 128];            // 32768
__device__ __align__(16) float g_W3p  [24 * 8 * 128];             // 24576, n>=162 zero

// ---------------- helpers ----------------
__device__ __host__ __forceinline__ int ppf(int k) {              // pair-permute within k8
    return (k & ~7) + ((k & 3) << 1) + ((k >> 2) & 1);
}
__device__ __forceinline__ float tf32r(float x) {
    uint32_t r;
    asm("cvt.rna.tf32.f32 %0, %1;" : "=r"(r) : "f"(x));
    return __uint_as_float(r);
}
__device__ __forceinline__ void mma8s(float* c, uint32_t a0, uint32_t a1, uint32_t a2,
                                      uint32_t a3, uint32_t b0, uint32_t b1) {
    asm volatile(
        "mma.sync.aligned.m16n8k8.row.col.f32.tf32.tf32.f32 "
        "{%0,%1,%2,%3}, {%4,%5,%6,%7}, {%8,%9}, {%0,%1,%2,%3};"
        : "+f"(c[0]), "+f"(c[1]), "+f"(c[2]), "+f"(c[3])
        : "r"(a0), "r"(a1), "r"(a2), "r"(a3), "r"(b0), "r"(b1));
}
__device__ __forceinline__ float sigm(float x) { return 1.0f / (1.0f + expf(-x)); }

// fragment-order index decode helper (host+device)
// i in [0, NT*KS2*128): returns n, k via refs
__device__ __forceinline__ void frag_decode(int i, int ks2_count, int& n, int& k) {
    int ntile = i / (ks2_count * 128);
    int rem   = i - ntile * ks2_count * 128;
    int ks2   = rem >> 7;
    int pos   = rem & 127;
    int lane  = pos >> 2, e4 = pos & 3;
    n = ntile * 8 + (lane >> 2);
    k = ((ks2 << 1) + (e4 >> 1)) * 8 + (lane & 3) + ((e4 & 1) << 2);
}

// ================= K0: pack weights (fragment order) =================
__global__ void pack_kernel(const float* __restrict__ W_ih, const float* __restrict__ W_hh,
                            const float* __restrict__ b_ih, const float* __restrict__ b_hh,
                            const float* __restrict__ W1, const float* __restrict__ W2,
                            const float* __restrict__ W3) {
    int i = blockIdx.x * blockDim.x + threadIdx.x;
    if (i < 2 * 86016) {                            // r / z merged gates, K=336
        int g = i / 86016, rem = i % 86016;
        int n, k; frag_decode(rem, 21, n, k);
        int row = g * 256 + n;
        float v = 0.0f;
        if (k < IN_DIM)      v = W_ih[(size_t)row * IN_DIM + k];
        else if (k >= KRNN && k < 336) v = W_hh[(size_t)row * HID + (k - KRNN)];
        g_Wg[(g ? WG_Z : WG_R) + rem] = tf32r(v);
        return;
    }
    i -= 2 * 86016;
    if (i < 20480) {                                // gi_n, K=80
        int n, k; frag_decode(i, 5, n, k);
        float v = (k < IN_DIM) ? W_ih[(size_t)(512 + n) * IN_DIM + k] : 0.0f;
        g_Wg[WG_GIN + i] = tf32r(v);
        return;
    }
    i -= 20480;
    if (i < 65536) {                                // gh_n, K=256
        int n, k; frag_decode(i, 16, n, k);
        g_Wg[WG_GHN + i] = tf32r(W_hh[(size_t)(512 + n) * HID + k]);
        return;
    }
    i -= 65536;
    if (i < 1024) {
        int j = i & 255, t = i >> 8;
        float v;
        if (t == 0)      v = b_ih[j]       + b_hh[j];
        else if (t == 1) v = b_ih[256 + j] + b_hh[256 + j];
        else if (t == 2) v = b_ih[512 + j];
        else             v = b_hh[512 + j];
        g_bias[i] = v;
        return;
    }
    i -= 1024;
    if (i < 65536) {                                // W1, K=256, N=256
        int n, k; frag_decode(i, 16, n, k);
        g_W1p[i] = tf32r(W1[(size_t)n * 256 + k]);
        return;
    }
    i -= 65536;
    if (i < 32768) {                                // W2, K=256, N=128
        int n, k; frag_decode(i, 16, n, k);
        g_W2p[i] = tf32r(W2[(size_t)n * 256 + k]);
        return;
    }
    i -= 32768;
    if (i < 24576) {                                // W3, K=128, N=192 (zero-padded)
        int n, k; frag_decode(i, 8, n, k);
        g_W3p[i] = (n < 162) ? tf32r(W3[(size_t)n * 128 + k]) : 0.0f;
    }
}
#define PACK_TOTAL (2*86016 + 20480 + 65536 + 1024 + 65536 + 32768 + 24576)

// ================= K1: per-row prep =================
__global__ __launch_bounds__(256)
void prep_kernel(const float* __restrict__ meas, const float* __restrict__ mask,
                 const float* __restrict__ dt,   const float* __restrict__ baselines,
                 const float* __restrict__ x_prev) {
    size_t r = (size_t)blockIdx.x * blockDim.x + threadIdx.x;
    if (r >= B_TOTAL) return;
    float dtv = dt[r];
    float xp[6], bl[12];
#pragma unroll
    for (int i = 0; i < 6; i++)  xp[i] = x_prev[r * 6 + i];
#pragma unroll
    for (int i = 0; i < 12; i++) bl[i] = baselines[r * 12 + i];
    float ds = dtv * NORM_R;
    float xm[6];
    xm[0] = fmaf(ds, xp[1], xp[0]); xm[1] = xp[1];
    xm[2] = fmaf(ds, xp[3], xp[2]); xm[3] = xp[3];
    xm[4] = fmaf(ds, xp[5], xp[4]); xm[5] = xp[5];
#pragma unroll
    for (int i = 0; i < 6; i++) g_xm[r * 6 + i] = xm[i];

    float yp[27];
#pragma unroll
    for (int p = 0; p < 3; p++) {
        float x0 = xm[0], x2 = xm[2], x4 = xm[4];
        if (p == 1) { x0 -= bl[0]; x2 -= bl[2]; x4 -= bl[4]; }
        if (p == 2) { x0 -= bl[6]; x2 -= bl[8]; x4 -= bl[10]; }
        float rxy = sqrtf(x0 * x0 + x2 * x2 + 1e-9f);
        float az  = atan2f(x2, x0) * (1.0f / PI_F);
        float el  = atan2f(x4, rxy) * (1.0f / PI_F);
        float rr  = sqrtf(x0 * x0 + x2 * x2 + x4 * x4 + 1e-9f);
        yp[p*9+0] = az; yp[p*9+1] = el; yp[p*9+2] = rr;
        yp[p*9+3] = az; yp[p*9+4] = el; yp[p*9+5] = 0.0f;
        yp[p*9+6] = az; yp[p*9+7] = 0.0f; yp[p*9+8] = 0.0f;
    }
    float* A = g_Arnn + r * KRNN;
#pragma unroll
    for (int m = 0; m < 27; m++) {
        float mv = meas[r * 27 + m];
        float mk = mask[r * 27 + m];
        float in = mv - yp[m];
        int mm = m % 9;
        bool ang = (mm == 0) | (mm == 1) | (mm == 3) | (mm == 4) | (mm == 6);
        if (ang) in = in - 2.0f * rintf(in * 0.5f);
        in *= mk;
        g_innov[r * 27 + m] = in;
        A[ppf(m)]      = tf32r(in);
        A[ppf(27 + m)] = tf32r(mk);
    }
    A[ppf(54)] = tf32r(dtv);
#pragma unroll
    for (int i = 0; i < 6; i++)  A[ppf(55 + i)] = tf32r(xm[i]);
#pragma unroll
    for (int i = 0; i < 12; i++) A[ppf(61 + i)] = tf32r(bl[i]);
#pragma unroll
    for (int i = 73; i < KRNN; i++) A[ppf(i)] = 0.0f;
}

// ================= K2: GRU (M=128/CTA) =================
#define GS 360
#define G_SMEM ((128 * GS + 1024) * 4)

__global__ __launch_bounds__(256, 1)
void gru_kernel(const float* __restrict__ hx, float* __restrict__ out_h) {
    extern __shared__ float sm[];
    float* sA    = sm;                              // [128][GS], logical [rnn 0..79 | hx 80..335]
    float* sBias = sm + 128 * GS;
    const int tid = threadIdx.x, lane = tid & 31, wid = tid >> 5;
    const int wm = wid & 3, wn = wid >> 2;
    const int r0 = blockIdx.x * 128;

    for (int t = tid; t < 128 * 20; t += 256) {
        int row = t / 20, s4 = (t % 20) * 4;
        float4 v = *(const float4*)(g_Arnn + (size_t)(r0 + row) * KRNN + s4);
        *(float4*)(sA + row * GS + s4) = v;
    }
    for (int t = tid; t < 128 * 64; t += 256) {
        int row = t >> 6, kq = (t & 63) << 2;
        float4 v = *(const float4*)(hx + (size_t)(r0 + row) * HID + kq);
        int base = row * GS + 80 + (kq & ~7) + ((kq >> 2) & 1);
        sA[base]     = tf32r(v.x);
        sA[base + 2] = tf32r(v.y);
        sA[base + 4] = tf32r(v.z);
        sA[base + 6] = tf32r(v.w);
    }
    for (int t = tid; t < 1024; t += 256) sBias[t] = g_bias[t];
    __syncthreads();

    const int koff  = (lane & 3) << 1;
    const int rowA0 = wm * 32 + (lane >> 2);

    for (int pass = 0; pass < 4; pass++) {
        const int jb  = pass * 64 + wn * 32;
        const int ntb = jb >> 3;                    // ntile base (4 tiles per warp)
        float Cr[2][4][4], Cz[2][4][4], Cn[2][4][4], Ch[2][4][4];
#pragma unroll
        for (int mt = 0; mt < 2; mt++)
#pragma unroll
            for (int nt = 0; nt < 4; nt++)
#pragma unroll
                for (int e = 0; e < 4; e++) {
                    Cr[mt][nt][e] = 0.f; Cz[mt][nt][e] = 0.f;
                    Cn[mt][nt][e] = 0.f; Ch[mt][nt][e] = 0.f;
                }

        const float* BrP = g_Wg + WG_R   + (size_t)ntb * 2688 + lane * 4;   // 21*128
        const float* BzP = g_Wg + WG_Z   + (size_t)ntb * 2688 + lane * 4;
        const float* BiP = g_Wg + WG_GIN + (size_t)ntb * 640  + lane * 4;   // 5*128
        const float* BhP = g_Wg + WG_GHN + (size_t)ntb * 2048 + lane * 4;   // 16*128

        // ---- r & z : K=336, 21 kstep-pairs ----
        for (int jj = 0; jj < 21; jj++) {
            uint4 br[4], bz[4];
#pragma unroll
            for (int nt = 0; nt < 4; nt++) {
                br[nt] = *(const uint4*)(BrP + nt * 2688 + jj * 128);
                bz[nt] = *(const uint4*)(BzP + nt * 2688 + jj * 128);
            }
            uint2 alo[2][2], ahi[2][2];
#pragma unroll
            for (int sub = 0; sub < 2; sub++)
#pragma unroll
                for (int mt = 0; mt < 2; mt++) {
                    const float* ap = sA + (rowA0 + mt * 16) * GS + (jj * 2 + sub) * 8 + koff;
                    alo[sub][mt] = *(const uint2*)ap;
                    ahi[sub][mt] = *(const uint2*)(ap + 8 * GS);
                }
#pragma unroll
            for (int nt = 0; nt < 4; nt++)
#pragma unroll
                for (int mt = 0; mt < 2; mt++) {
                    mma8s(Cr[mt][nt], alo[0][mt].x, ahi[0][mt].x, alo[0][mt].y, ahi[0][mt].y, br[nt].x, br[nt].y);
                    mma8s(Cr[mt][nt], alo[1][mt].x, ahi[1][mt].x, alo[1][mt].y, ahi[1][mt].y, br[nt].z, br[nt].w);
                    mma8s(Cz[mt][nt], alo[0][mt].x, ahi[0][mt].x, alo[0][mt].y, ahi[0][mt].y, bz[nt].x, bz[nt].y);
                    mma8s(Cz[mt][nt], alo[1][mt].x, ahi[1][mt].x, alo[1][mt].y, ahi[1][mt].y, bz[nt].z, bz[nt].w);
                }
        }
        // ---- gi_n : K=80, 5 kstep-pairs ----
        for (int jj = 0; jj < 5; jj++) {
            uint4 bi[4];
#pragma unroll
            for (int nt = 0; nt < 4; nt++)
                bi[nt] = *(const uint4*)(BiP + nt * 640 + jj * 128);
            uint2 alo[2][2], ahi[2][2];
#pragma unroll
            for (int sub = 0; sub < 2; sub++)
#pragma unroll
                for (int mt = 0; mt < 2; mt++) {
                    const float* ap = sA + (rowA0 + mt * 16) * GS + (jj * 2 + sub) * 8 + koff;
                    alo[sub][mt] = *(const uint2*)ap;
                    ahi[sub][mt] = *(const uint2*)(ap + 8 * GS);
                }
#pragma unroll
            for (int nt = 0; nt < 4; nt++)
#pragma unroll
                for (int mt = 0; mt < 2; mt++) {
                    mma8s(Cn[mt][nt], alo[0][mt].x, ahi[0][mt].x, alo[0][mt].y, ahi[0][mt].y, bi[nt].x, bi[nt].y);
                    mma8s(Cn[mt][nt], alo[1][mt].x, ahi[1][mt].x, alo[1][mt].y, ahi[1][mt].y, bi[nt].z, bi[nt].w);
                }
        }
        // ---- gh_n : K=256, 16 kstep-pairs, A offset +80 ----
        for (int jj = 0; jj < 16; jj++) {
            uint4 bh[4];
#pragma unroll
            for (int nt = 0; nt < 4; nt++)
                bh[nt] = *(const uint4*)(BhP + nt * 2048 + jj * 128);
            uint2 alo[2][2], ahi[2][2];
#pragma unroll
            for (int sub = 0; sub < 2; sub++)
#pragma unroll
                for (int mt = 0; mt < 2; mt++) {
                    const float* ap = sA + (rowA0 + mt * 16) * GS + 80 + (jj * 2 + sub) * 8 + koff;
                    alo[sub][mt] = *(const uint2*)ap;
                    ahi[sub][mt] = *(const uint2*)(ap + 8 * GS);
                }
#pragma unroll
            for (int nt = 0; nt < 4; nt++)
#pragma unroll
                for (int mt = 0; mt < 2; mt++) {
                    mma8s(Ch[mt][nt], alo[0][mt].x, ahi[0][mt].x, alo[0][mt].y, ahi[0][mt].y, bh[nt].x, bh[nt].y);
                    mma8s(Ch[mt][nt], alo[1][mt].x, ahi[1][mt].x, alo[1][mt].y, ahi[1][mt].y, bh[nt].z, bh[nt].w);
                }
        }
        // ---- epilogue ----
#pragma unroll
        for (int mt = 0; mt < 2; mt++)
#pragma unroll
            for (int nt = 0; nt < 4; nt++)
#pragma unroll
                for (int half = 0; half < 2; half++) {
                    const int row = rowA0 + mt * 16 + half * 8;
                    const int jc  = jb + nt * 8 + ((lane & 3) << 1);
                    float h2[2];
#pragma unroll
                    for (int e = 0; e < 2; e++) {
                        const int j = jc + e;
                        const int idx = half * 2 + e;
                        float rg = sigm(Cr[mt][nt][idx] + sBias[j]);
                        float zg = sigm(Cz[mt][nt][idx] + sBias[256 + j]);
                        float nn = tanhf(Cn[mt][nt][idx] + sBias[512 + j]
                                         + rg * (Ch[mt][nt][idx] + sBias[768 + j]));
                        float hxv = sA[row * GS + 80 + (j & ~7) + ((j & 3) << 1) + ((j >> 2) & 1)];
                        h2[e] = (1.0f - zg) * nn + zg * hxv;
                    }
                    *(float2*)(out_h + (size_t)(r0 + row) * HID + jc) = make_float2(h2[0], h2[1]);
                }
    }
}

// ================= K3: LN + MLP + gain head (M=64/CTA) =================
#define S1 264
#define S3 136
#define SKV 200
#define OFF_A2  (64 * S1)
#define OFF_A3  (OFF_A2 + 64 * S1)
#define OFF_INN (OFF_A3 + 64 * S3)
#define M_SMEM  ((OFF_INN + 64 * 28) * 4)

__global__ __launch_bounds__(256, 1)
void mlp_kernel(const float* __restrict__ h_in,
                const float* __restrict__ ln_g, const float* __restrict__ ln_b,
                const float* __restrict__ b1, const float* __restrict__ b2,
                const float* __restrict__ b3, float* __restrict__ out_x) {
    extern __shared__ float sm[];
    float* sA1  = sm;                 // [64][S1] h_ln, later reused as kv [64][SKV]
    float* sA2  = sm + OFF_A2;        // [64][S1] f1
    float* sA3  = sm + OFF_A3;        // [64][S3] f2
    float* sInn = sm + OFF_INN;       // [64][28]
    const int tid = threadIdx.x, lane = tid & 31, wid = tid >> 5;
    const int wm = wid & 3, wn = wid >> 2;
    const int r0 = blockIdx.x * 64;

    for (int t = tid; t < 64 * 64; t += 256) {
        int row = t >> 6, kq = (t & 63) << 2;
        float4 v = *(const float4*)(h_in + (size_t)(r0 + row) * HID + kq);
        int base = row * S1 + (kq & ~7) + ((kq >> 2) & 1);
        sA1[base] = v.x; sA1[base + 2] = v.y; sA1[base + 4] = v.z; sA1[base + 6] = v.w;
    }
    for (int t = tid; t < 64 * 27; t += 256) {
        int row = t / 27, m = t % 27;
        sInn[row * 28 + m] = g_innov[(size_t)(r0 + row) * 27 + m];
    }
    __syncthreads();

    {
        const int row = tid >> 2, q = tid & 3;
        float s = 0.f, sq = 0.f;
        for (int i = 0; i < 64; i++) {
            float v = sA1[row * S1 + q * 64 + i];
            s += v; sq = fmaf(v, v, sq);
        }
        s  += __shfl_xor_sync(0xffffffffu, s, 1);  sq += __shfl_xor_sync(0xffffffffu, sq, 1);
        s  += __shfl_xor_sync(0xffffffffu, s, 2);  sq += __shfl_xor_sync(0xffffffffu, sq, 2);
        float mu = s * (1.0f / 256.0f);
        float var = sq * (1.0f / 256.0f) - mu * mu;
        float rs = rsqrtf(var + 1e-5f);
        for (int i = 0; i < 64; i++) {
            int sp = q * 64 + i;
            int lc = (sp & ~7) + ((sp & 1) << 2) + ((sp >> 1) & 3);   // inverse perm
            float v = sA1[row * S1 + sp];
            sA1[row * S1 + sp] = tf32r((v - mu) * rs * __ldg(ln_g + lc) + __ldg(ln_b + lc));
        }
    }
    __syncthreads();

    const int koff  = (lane & 3) << 1;
    const int rowA0 = wm * 16 + (lane >> 2);

    // ---- MLP1: N=256 (4 passes), K=256 (16 pairs), A=sA1 -> f1 in sA2 ----
    for (int p = 0; p < 4; p++) {
        const int nb  = p * 64 + wn * 32;
        const int ntb = nb >> 3;
        float C[4][4];
#pragma unroll
        for (int nt = 0; nt < 4; nt++)
#pragma unroll
            for (int e = 0; e < 4; e++) C[nt][e] = 0.f;
        const float* BP = g_W1p + (size_t)ntb * 2048 + lane * 4;
        for (int jj = 0; jj < 16; jj++) {
            uint4 b[4];
#pragma unroll
            for (int nt = 0; nt < 4; nt++) b[nt] = *(const uint4*)(BP + nt * 2048 + jj * 128);
            uint2 alo[2], ahi[2];
#pragma unroll
            for (int sub = 0; sub < 2; sub++) {
                const float* ap = sA1 + rowA0 * S1 + (jj * 2 + sub) * 8 + koff;
                alo[sub] = *(const uint2*)ap;
                ahi[sub] = *(const uint2*)(ap + 8 * S1);
            }
#pragma unroll
            for (int nt = 0; nt < 4; nt++) {
                mma8s(C[nt], alo[0].x, ahi[0].x, alo[0].y, ahi[0].y, b[nt].x, b[nt].y);
                mma8s(C[nt], alo[1].x, ahi[1].x, alo[1].y, ahi[1].y, b[nt].z, b[nt].w);
            }
        }
#pragma unroll
        for (int nt = 0; nt < 4; nt++)
#pragma unroll
            for (int half = 0; half < 2; half++) {
                const int row = rowA0 + half * 8;
                const int j0  = nb + nt * 8 + koff;
#pragma unroll
                for (int e = 0; e < 2; e++) {
                    int j = j0 + e;
                    float f = fmaxf(C[nt][half * 2 + e] + __ldg(b1 + j), 0.0f);
                    sA2[row * S1 + (j & ~7) + ((j & 3) << 1) + ((j >> 2) & 1)] = tf32r(f);
                }
            }
    }
    __syncthreads();

    // ---- MLP2: N=128 (2 passes), K=256 ----
    for (int p = 0; p < 2; p++) {
        const int nb  = p * 64 + wn * 32;
        const int ntb = nb >> 3;
        float C[4][4];
#pragma unroll
        for (int nt = 0; nt < 4; nt++)
#pragma unroll
            for (int e = 0; e < 4; e++) C[nt][e] = 0.f;
        const float* BP = g_W2p + (size_t)ntb * 2048 + lane * 4;
        for (int jj = 0; jj < 16; jj++) {
            uint4 b[4];
#pragma unroll
            for (int nt = 0; nt < 4; nt++) b[nt] = *(const uint4*)(BP + nt * 2048 + jj * 128);
            uint2 alo[2], ahi[2];
#pragma unroll
            for (int sub = 0; sub < 2; sub++) {
                const float* ap = sA2 + rowA0 * S1 + (jj * 2 + sub) * 8 + koff;
                alo[sub] = *(const uint2*)ap;
                ahi[sub] = *(const uint2*)(ap + 8 * S1);
            }
#pragma unroll
            for (int nt = 0; nt < 4; nt++) {
                mma8s(C[nt], alo[0].x, ahi[0].x, alo[0].y, ahi[0].y, b[nt].x, b[nt].y);
                mma8s(C[nt], alo[1].x, ahi[1].x, alo[1].y, ahi[1].y, b[nt].z, b[nt].w);
            }
        }
#pragma unroll
        for (int nt = 0; nt < 4; nt++)
#pragma unroll
            for (int half = 0; half < 2; half++) {
                const int row = rowA0 + half * 8;
                const int j0  = nb + nt * 8 + koff;
#pragma unroll
                for (int e = 0; e < 2; e++) {
                    int j = j0 + e;
                    float f = fmaxf(C[nt][half * 2 + e] + __ldg(b2 + j), 0.0f);
                    sA3[row * S3 + (j & ~7) + ((j & 3) << 1) + ((j >> 2) & 1)] = tf32r(f);
                }
            }
    }
    __syncthreads();

    // ---- MLP3: N=192 (3 passes), K=128 (8 pairs) ----
    for (int p = 0; p < 3; p++) {
        const int nb  = p * 64 + wn * 32;
        const int ntb = nb >> 3;
        float C[4][4];
#pragma unroll
        for (int nt = 0; nt < 4; nt++)
#pragma unroll
            for (int e = 0; e < 4; e++) C[nt][e] = 0.f;
        const float* BP = g_W3p + (size_t)ntb * 1024 + lane * 4;
        for (int jj = 0; jj < 8; jj++) {
            uint4 b[4];
#pragma unroll
            for (int nt = 0; nt < 4; nt++) b[nt] = *(const uint4*)(BP + nt * 1024 + jj * 128);
            uint2 alo[2], ahi[2];
#pragma unroll
            for (int sub = 0; sub < 2; sub++) {
                const float* ap = sA3 + rowA0 * S3 + (jj * 2 + sub) * 8 + koff;
                alo[sub] = *(const uint2*)ap;
                ahi[sub] = *(const uint2*)(ap + 8 * S3);
            }
#pragma unroll
            for (int nt = 0; nt < 4; nt++) {
                mma8s(C[nt], alo[0].x, ahi[0].x, alo[0].y, ahi[0].y, b[nt].x, b[nt].y);
                mma8s(C[nt], alo[1].x, ahi[1].x, alo[1].y, ahi[1].y, b[nt].z, b[nt].w);
            }
        }
#pragma unroll
        for (int nt = 0; nt < 4; nt++)
#pragma unroll
            for (int half = 0; half < 2; half++) {
                const int row = rowA0 + half * 8;
                const int j0  = nb + nt * 8 + koff;
#pragma unroll
                for (int e = 0; e < 2; e++) {
                    int j = j0 + e;
                    if (j < 162) {
                        float kv = C[nt][half * 2 + e] + __ldg(b3 + j);
                        sA1[row * SKV + j] = fminf(fmaxf(kv, -3.0f), 3.0f);
                    }
                }
            }
    }
    __syncthreads();

    for (int t = tid; t < 384; t += 256) {
        const int row = t & 63, s = t >> 6;
        float corr = 0.f;
#pragma unroll
        for (int m = 0; m < 27; m++)
            corr = fmaf(sA1[row * SKV + s * 27 + m], sInn[row * 28 + m], corr);
        float xmv = g_xm[(size_t)(r0 + row) * 6 + s];
        out_x[(size_t)(r0 + row) * 6 + s] = fminf(fmaxf(xmv + corr, -5.0f), 5.0f);
    }
}

// ================= launch =================
extern "C" void kernel_launch(void* const* d_in, const int* in_sizes, int n_in,
                              void* d_out, int out_size)
{
    (void)in_sizes; (void)n_in; (void)out_size;
    const float* meas      = (const float*)d_in[0];
    const float* mask      = (const float*)d_in[1];
    const float* dtv       = (const float*)d_in[2];
    const float* baselines = (const float*)d_in[3];
    const float* x_prev    = (const float*)d_in[4];
    const float* hx        = (const float*)d_in[5];
    const float* W_ih      = (const float*)d_in[6];
    const float* W_hh      = (const float*)d_in[7];
    const float* b_ih      = (const float*)d_in[8];
    const float* b_hh      = (const float*)d_in[9];
    const float* ln_g      = (const float*)d_in[10];
    const float* ln_b      = (const float*)d_in[11];
    const float* W1        = (const float*)d_in[12];
    const float* b1        = (const float*)d_in[13];
    const float* W2        = (const float*)d_in[14];
    const float* b2        = (const float*)d_in[15];
    const float* W3        = (const float*)d_in[16];
    const float* b3        = (const float*)d_in[17];

    float* out   = (float*)d_out;
    float* out_x = out;                            // [B, 6]
    float* out_h = out + (size_t)B_TOTAL * 6;      // [B, 256]

    pack_kernel<<<(PACK_TOTAL + 255) / 256, 256>>>(W_ih, W_hh, b_ih, b_hh, W1, W2, W3);
    prep_kernel<<<B_TOTAL / 256, 256>>>(meas, mask, dtv, baselines, x_prev);

    cudaFuncSetAttribute(gru_kernel, cudaFuncAttributeMaxDynamicSharedMemorySize, G_SMEM);
    gru_kernel<<<B_TOTAL / 128, 256, G_SMEM>>>(hx, out_h);

    cudaFuncSetAttribute(mlp_kernel, cudaFuncAttributeMaxDynamicSharedMemorySize, M_SMEM);
    mlp_kernel<<<B_TOTAL / 64, 256, M_SMEM>>>(out_h, ln_g, ln_b, b1, b2, b3, out_x);
}

// round 8
// speedup vs baseline: 1.9575x; 1.0891x over previous
#include <cuda_runtime.h>
#include <stdint.h>
#include <math.h>

#define B_TOTAL   262144
#define IN_DIM    73
#define KRNN      80
#define HID       256
#define PI_F      3.14159265358979323846f
#define NORM_R    (500.0f/150000.0f)

// Fragment-order packed weights: [ntile][ks2][128] with pos = lane*4 + e4
// value(lane,e4) = W[n = ntile*8 + lane/4][k = (2*ks2 + (e4>>1))*8 + lane%4 + 4*(e4&1)]
#define WG_R      0            // 32 ntiles x 21 ks2 x 128 = 86016   (K=336: [ih|pad|hh])
#define WG_Z      86016        // 32 x 21 x 128
#define WG_GIN    172032       // 32 x 5  x 128 = 20480              (K=80)
#define WG_GHN    192512       // 32 x 16 x 128 = 65536              (K=256)
#define WG_TOTAL  258048

// ---------------- device scratch ----------------
__device__ __align__(16) float g_Arnn [(size_t)B_TOTAL * KRNN];   // pair-permuted, tf32
__device__ __align__(16) float g_innov[(size_t)B_TOTAL * 27];
__device__ __align__(16) float g_xm   [(size_t)B_TOTAL * 6];
__device__ __align__(16) float g_Wg   [WG_TOTAL];
__device__ __align__(16) float g_bias [1024];
__device__ __align__(16) float g_W1p  [32 * 16 * 128];            // 65536
__device__ __align__(16) float g_W2p  [16 * 16 * 128];            // 32768
__device__ __align__(16) float g_W3p  [24 * 8 * 128];             // 24576, n>=162 zero

// ---------------- helpers ----------------
__device__ __host__ __forceinline__ int ppf(int k) {              // pair-permute within k8
    return (k & ~7) + ((k & 3) << 1) + ((k >> 2) & 1);
}
__device__ __forceinline__ float tf32r(float x) {
    uint32_t r;
    asm("cvt.rna.tf32.f32 %0, %1;" : "=r"(r) : "f"(x));
    return __uint_as_float(r);
}
__device__ __forceinline__ void mma8s(float* c, uint32_t a0, uint32_t a1, uint32_t a2,
                                      uint32_t a3, uint32_t b0, uint32_t b1) {
    asm volatile(
        "mma.sync.aligned.m16n8k8.row.col.f32.tf32.tf32.f32 "
        "{%0,%1,%2,%3}, {%4,%5,%6,%7}, {%8,%9}, {%0,%1,%2,%3};"
        : "+f"(c[0]), "+f"(c[1]), "+f"(c[2]), "+f"(c[3])
        : "r"(a0), "r"(a1), "r"(a2), "r"(a3), "r"(b0), "r"(b1));
}
__device__ __forceinline__ float sigm(float x) { return 1.0f / (1.0f + expf(-x)); }

// fragment-order index decode helper
__device__ __forceinline__ void frag_decode(int i, int ks2_count, int& n, int& k) {
    int ntile = i / (ks2_count * 128);
    int rem   = i - ntile * ks2_count * 128;
    int ks2   = rem >> 7;
    int pos   = rem & 127;
    int lane  = pos >> 2, e4 = pos & 3;
    n = ntile * 8 + (lane >> 2);
    k = ((ks2 << 1) + (e4 >> 1)) * 8 + (lane & 3) + ((e4 & 1) << 2);
}

// ================= K0: pack weights (fragment order) =================
__global__ void pack_kernel(const float* __restrict__ W_ih, const float* __restrict__ W_hh,
                            const float* __restrict__ b_ih, const float* __restrict__ b_hh,
                            const float* __restrict__ W1, const float* __restrict__ W2,
                            const float* __restrict__ W3) {
    int i = blockIdx.x * blockDim.x + threadIdx.x;
    if (i < 2 * 86016) {                            // r / z merged gates, K=336
        int g = i / 86016, rem = i % 86016;
        int n, k; frag_decode(rem, 21, n, k);
        int row = g * 256 + n;
        float v = 0.0f;
        if (k < IN_DIM)      v = W_ih[(size_t)row * IN_DIM + k];
        else if (k >= KRNN && k < 336) v = W_hh[(size_t)row * HID + (k - KRNN)];
        g_Wg[(g ? WG_Z : WG_R) + rem] = tf32r(v);
        return;
    }
    i -= 2 * 86016;
    if (i < 20480) {                                // gi_n, K=80
        int n, k; frag_decode(i, 5, n, k);
        float v = (k < IN_DIM) ? W_ih[(size_t)(512 + n) * IN_DIM + k] : 0.0f;
        g_Wg[WG_GIN + i] = tf32r(v);
        return;
    }
    i -= 20480;
    if (i < 65536) {                                // gh_n, K=256
        int n, k; frag_decode(i, 16, n, k);
        g_Wg[WG_GHN + i] = tf32r(W_hh[(size_t)(512 + n) * HID + k]);
        return;
    }
    i -= 65536;
    if (i < 1024) {
        int j = i & 255, t = i >> 8;
        float v;
        if (t == 0)      v = b_ih[j]       + b_hh[j];
        else if (t == 1) v = b_ih[256 + j] + b_hh[256 + j];
        else if (t == 2) v = b_ih[512 + j];
        else             v = b_hh[512 + j];
        g_bias[i] = v;
        return;
    }
    i -= 1024;
    if (i < 65536) {                                // W1, K=256, N=256
        int n, k; frag_decode(i, 16, n, k);
        g_W1p[i] = tf32r(W1[(size_t)n * 256 + k]);
        return;
    }
    i -= 65536;
    if (i < 32768) {                                // W2, K=256, N=128
        int n, k; frag_decode(i, 16, n, k);
        g_W2p[i] = tf32r(W2[(size_t)n * 256 + k]);
        return;
    }
    i -= 32768;
    if (i < 24576) {                                // W3, K=128, N=192 (zero-padded)
        int n, k; frag_decode(i, 8, n, k);
        g_W3p[i] = (n < 162) ? tf32r(W3[(size_t)n * 128 + k]) : 0.0f;
    }
}
#define PACK_TOTAL (2*86016 + 20480 + 65536 + 1024 + 65536 + 32768 + 24576)

// ================= K1: per-row prep =================
__global__ __launch_bounds__(256)
void prep_kernel(const float* __restrict__ meas, const float* __restrict__ mask,
                 const float* __restrict__ dt,   const float* __restrict__ baselines,
                 const float* __restrict__ x_prev) {
    size_t r = (size_t)blockIdx.x * blockDim.x + threadIdx.x;
    if (r >= B_TOTAL) return;
    float dtv = dt[r];
    float xp[6], bl[12];
#pragma unroll
    for (int i = 0; i < 6; i++)  xp[i] = x_prev[r * 6 + i];
#pragma unroll
    for (int i = 0; i < 12; i++) bl[i] = baselines[r * 12 + i];
    float ds = dtv * NORM_R;
    float xm[6];
    xm[0] = fmaf(ds, xp[1], xp[0]); xm[1] = xp[1];
    xm[2] = fmaf(ds, xp[3], xp[2]); xm[3] = xp[3];
    xm[4] = fmaf(ds, xp[5], xp[4]); xm[5] = xp[5];
#pragma unroll
    for (int i = 0; i < 6; i++) g_xm[r * 6 + i] = xm[i];

    float yp[27];
#pragma unroll
    for (int p = 0; p < 3; p++) {
        float x0 = xm[0], x2 = xm[2], x4 = xm[4];
        if (p == 1) { x0 -= bl[0]; x2 -= bl[2]; x4 -= bl[4]; }
        if (p == 2) { x0 -= bl[6]; x2 -= bl[8]; x4 -= bl[10]; }
        float rxy = sqrtf(x0 * x0 + x2 * x2 + 1e-9f);
        float az  = atan2f(x2, x0) * (1.0f / PI_F);
        float el  = atan2f(x4, rxy) * (1.0f / PI_F);
        float rr  = sqrtf(x0 * x0 + x2 * x2 + x4 * x4 + 1e-9f);
        yp[p*9+0] = az; yp[p*9+1] = el; yp[p*9+2] = rr;
        yp[p*9+3] = az; yp[p*9+4] = el; yp[p*9+5] = 0.0f;
        yp[p*9+6] = az; yp[p*9+7] = 0.0f; yp[p*9+8] = 0.0f;
    }
    float* A = g_Arnn + r * KRNN;
#pragma unroll
    for (int m = 0; m < 27; m++) {
        float mv = meas[r * 27 + m];
        float mk = mask[r * 27 + m];
        float in = mv - yp[m];
        int mm = m % 9;
        bool ang = (mm == 0) | (mm == 1) | (mm == 3) | (mm == 4) | (mm == 6);
        if (ang) in = in - 2.0f * rintf(in * 0.5f);
        in *= mk;
        g_innov[r * 27 + m] = in;
        A[ppf(m)]      = tf32r(in);
        A[ppf(27 + m)] = tf32r(mk);
    }
    A[ppf(54)] = tf32r(dtv);
#pragma unroll
    for (int i = 0; i < 6; i++)  A[ppf(55 + i)] = tf32r(xm[i]);
#pragma unroll
    for (int i = 0; i < 12; i++) A[ppf(61 + i)] = tf32r(bl[i]);
#pragma unroll
    for (int i = 73; i < KRNN; i++) A[ppf(i)] = 0.0f;
}

// ================= K2: GRU (M=128/CTA) =================
#define GS 360
#define G_SMEM ((128 * GS + 1024) * 4)

__global__ __launch_bounds__(256, 1)
void gru_kernel(const float* __restrict__ hx, float* __restrict__ out_h) {
    extern __shared__ float sm[];
    float* sA    = sm;                              // [128][GS], logical [rnn 0..79 | hx 80..335]
    float* sBias = sm + 128 * GS;
    const int tid = threadIdx.x, lane = tid & 31, wid = tid >> 5;
    const int wm = wid & 3, wn = wid >> 2;
    const int r0 = blockIdx.x * 128;

    for (int t = tid; t < 128 * 20; t += 256) {
        int row = t / 20, s4 = (t % 20) * 4;
        float4 v = *(const float4*)(g_Arnn + (size_t)(r0 + row) * KRNN + s4);
        *(float4*)(sA + row * GS + s4) = v;
    }
    for (int t = tid; t < 128 * 64; t += 256) {
        int row = t >> 6, kq = (t & 63) << 2;
        float4 v = *(const float4*)(hx + (size_t)(r0 + row) * HID + kq);
        int base = row * GS + 80 + (kq & ~7) + ((kq >> 2) & 1);
        sA[base]     = tf32r(v.x);
        sA[base + 2] = tf32r(v.y);
        sA[base + 4] = tf32r(v.z);
        sA[base + 6] = tf32r(v.w);
    }
    for (int t = tid; t < 1024; t += 256) sBias[t] = g_bias[t];
    __syncthreads();

    const int koff  = (lane & 3) << 1;
    const int rowA0 = wm * 32 + (lane >> 2);

    for (int pass = 0; pass < 4; pass++) {
        const int jb  = pass * 64 + wn * 32;
        const int ntb = jb >> 3;
        float Cr[2][4][4], Cz[2][4][4], Cn[2][4][4], Ch[2][4][4];
#pragma unroll
        for (int mt = 0; mt < 2; mt++)
#pragma unroll
            for (int nt = 0; nt < 4; nt++)
#pragma unroll
                for (int e = 0; e < 4; e++) {
                    Cr[mt][nt][e] = 0.f; Cz[mt][nt][e] = 0.f;
                    Cn[mt][nt][e] = 0.f; Ch[mt][nt][e] = 0.f;
                }

        const float* BrP = g_Wg + WG_R   + (size_t)ntb * 2688 + lane * 4;
        const float* BzP = g_Wg + WG_Z   + (size_t)ntb * 2688 + lane * 4;
        const float* BiP = g_Wg + WG_GIN + (size_t)ntb * 640  + lane * 4;
        const float* BhP = g_Wg + WG_GHN + (size_t)ntb * 2048 + lane * 4;

        // ---- r & z : K=336, 21 kstep-pairs, distance-1 B prefetch ----
        {
            uint4 br[4], bz[4];
#pragma unroll
            for (int nt = 0; nt < 4; nt++) {
                br[nt] = *(const uint4*)(BrP + nt * 2688);
                bz[nt] = *(const uint4*)(BzP + nt * 2688);
            }
            for (int jj = 0; jj < 21; jj++) {
                const int jn = (jj < 20) ? jj + 1 : 20;
                uint4 brn[4], bzn[4];
#pragma unroll
                for (int nt = 0; nt < 4; nt++) {
                    brn[nt] = *(const uint4*)(BrP + nt * 2688 + jn * 128);
                    bzn[nt] = *(const uint4*)(BzP + nt * 2688 + jn * 128);
                }
                uint2 alo[2][2], ahi[2][2];
#pragma unroll
                for (int sub = 0; sub < 2; sub++)
#pragma unroll
                    for (int mt = 0; mt < 2; mt++) {
                        const float* ap = sA + (rowA0 + mt * 16) * GS + (jj * 2 + sub) * 8 + koff;
                        alo[sub][mt] = *(const uint2*)ap;
                        ahi[sub][mt] = *(const uint2*)(ap + 8 * GS);
                    }
#pragma unroll
                for (int nt = 0; nt < 4; nt++)
#pragma unroll
                    for (int mt = 0; mt < 2; mt++) {
                        mma8s(Cr[mt][nt], alo[0][mt].x, ahi[0][mt].x, alo[0][mt].y, ahi[0][mt].y, br[nt].x, br[nt].y);
                        mma8s(Cr[mt][nt], alo[1][mt].x, ahi[1][mt].x, alo[1][mt].y, ahi[1][mt].y, br[nt].z, br[nt].w);
                        mma8s(Cz[mt][nt], alo[0][mt].x, ahi[0][mt].x, alo[0][mt].y, ahi[0][mt].y, bz[nt].x, bz[nt].y);
                        mma8s(Cz[mt][nt], alo[1][mt].x, ahi[1][mt].x, alo[1][mt].y, ahi[1][mt].y, bz[nt].z, bz[nt].w);
                    }
#pragma unroll
                for (int nt = 0; nt < 4; nt++) { br[nt] = brn[nt]; bz[nt] = bzn[nt]; }
            }
        }
        // ---- gi_n : K=80, 5 kstep-pairs ----
        {
            uint4 bi[4];
#pragma unroll
            for (int nt = 0; nt < 4; nt++) bi[nt] = *(const uint4*)(BiP + nt * 640);
            for (int jj = 0; jj < 5; jj++) {
                const int jn = (jj < 4) ? jj + 1 : 4;
                uint4 bin[4];
#pragma unroll
                for (int nt = 0; nt < 4; nt++)
                    bin[nt] = *(const uint4*)(BiP + nt * 640 + jn * 128);
                uint2 alo[2][2], ahi[2][2];
#pragma unroll
                for (int sub = 0; sub < 2; sub++)
#pragma unroll
                    for (int mt = 0; mt < 2; mt++) {
                        const float* ap = sA + (rowA0 + mt * 16) * GS + (jj * 2 + sub) * 8 + koff;
                        alo[sub][mt] = *(const uint2*)ap;
                        ahi[sub][mt] = *(const uint2*)(ap + 8 * GS);
                    }
#pragma unroll
                for (int nt = 0; nt < 4; nt++)
#pragma unroll
                    for (int mt = 0; mt < 2; mt++) {
                        mma8s(Cn[mt][nt], alo[0][mt].x, ahi[0][mt].x, alo[0][mt].y, ahi[0][mt].y, bi[nt].x, bi[nt].y);
                        mma8s(Cn[mt][nt], alo[1][mt].x, ahi[1][mt].x, alo[1][mt].y, ahi[1][mt].y, bi[nt].z, bi[nt].w);
                    }
#pragma unroll
                for (int nt = 0; nt < 4; nt++) bi[nt] = bin[nt];
            }
        }
        // ---- gh_n : K=256, 16 kstep-pairs, A offset +80 ----
        {
            uint4 bh[4];
#pragma unroll
            for (int nt = 0; nt < 4; nt++) bh[nt] = *(const uint4*)(BhP + nt * 2048);
            for (int jj = 0; jj < 16; jj++) {
                const int jn = (jj < 15) ? jj + 1 : 15;
                uint4 bhn[4];
#pragma unroll
                for (int nt = 0; nt < 4; nt++)
                    bhn[nt] = *(const uint4*)(BhP + nt * 2048 + jn * 128);
                uint2 alo[2][2], ahi[2][2];
#pragma unroll
                for (int sub = 0; sub < 2; sub++)
#pragma unroll
                    for (int mt = 0; mt < 2; mt++) {
                        const float* ap = sA + (rowA0 + mt * 16) * GS + 80 + (jj * 2 + sub) * 8 + koff;
                        alo[sub][mt] = *(const uint2*)ap;
                        ahi[sub][mt] = *(const uint2*)(ap + 8 * GS);
                    }
#pragma unroll
                for (int nt = 0; nt < 4; nt++)
#pragma unroll
                    for (int mt = 0; mt < 2; mt++) {
                        mma8s(Ch[mt][nt], alo[0][mt].x, ahi[0][mt].x, alo[0][mt].y, ahi[0][mt].y, bh[nt].x, bh[nt].y);
                        mma8s(Ch[mt][nt], alo[1][mt].x, ahi[1][mt].x, alo[1][mt].y, ahi[1][mt].y, bh[nt].z, bh[nt].w);
                    }
#pragma unroll
                for (int nt = 0; nt < 4; nt++) bh[nt] = bhn[nt];
            }
        }
        // ---- epilogue ----
#pragma unroll
        for (int mt = 0; mt < 2; mt++)
#pragma unroll
            for (int nt = 0; nt < 4; nt++)
#pragma unroll
                for (int half = 0; half < 2; half++) {
                    const int row = rowA0 + mt * 16 + half * 8;
                    const int jc  = jb + nt * 8 + ((lane & 3) << 1);
                    float h2[2];
#pragma unroll
                    for (int e = 0; e < 2; e++) {
                        const int j = jc + e;
                        const int idx = half * 2 + e;
                        float rg = sigm(Cr[mt][nt][idx] + sBias[j]);
                        float zg = sigm(Cz[mt][nt][idx] + sBias[256 + j]);
                        float nn = tanhf(Cn[mt][nt][idx] + sBias[512 + j]
                                         + rg * (Ch[mt][nt][idx] + sBias[768 + j]));
                        float hxv = sA[row * GS + 80 + (j & ~7) + ((j & 3) << 1) + ((j >> 2) & 1)];
                        h2[e] = (1.0f - zg) * nn + zg * hxv;
                    }
                    *(float2*)(out_h + (size_t)(r0 + row) * HID + jc) = make_float2(h2[0], h2[1]);
                }
    }
}

// ================= K3: LN + MLP + gain head (M=64/CTA) =================
#define S1 264
#define S3 136
#define SKV 200
#define OFF_A2  (64 * S1)
#define OFF_A3  (OFF_A2 + 64 * S1)
#define OFF_INN (OFF_A3 + 64 * S3)
#define M_SMEM  ((OFF_INN + 64 * 28) * 4)

__global__ __launch_bounds__(256, 1)
void mlp_kernel(const float* __restrict__ h_in,
                const float* __restrict__ ln_g, const float* __restrict__ ln_b,
                const float* __restrict__ b1, const float* __restrict__ b2,
                const float* __restrict__ b3, float* __restrict__ out_x) {
    extern __shared__ float sm[];
    float* sA1  = sm;                 // [64][S1] h_ln, later reused as kv [64][SKV]
    float* sA2  = sm + OFF_A2;        // [64][S1] f1
    float* sA3  = sm + OFF_A3;        // [64][S3] f2
    float* sInn = sm + OFF_INN;       // [64][28]
    const int tid = threadIdx.x, lane = tid & 31, wid = tid >> 5;
    const int wm = wid & 3, wn = wid >> 2;
    const int r0 = blockIdx.x * 64;

    for (int t = tid; t < 64 * 64; t += 256) {
        int row = t >> 6, kq = (t & 63) << 2;
        float4 v = *(const float4*)(h_in + (size_t)(r0 + row) * HID + kq);
        int base = row * S1 + (kq & ~7) + ((kq >> 2) & 1);
        sA1[base] = v.x; sA1[base + 2] = v.y; sA1[base + 4] = v.z; sA1[base + 6] = v.w;
    }
    for (int t = tid; t < 64 * 27; t += 256) {
        int row = t / 27, m = t % 27;
        sInn[row * 28 + m] = g_innov[(size_t)(r0 + row) * 27 + m];
    }
    __syncthreads();

    {
        const int row = tid >> 2, q = tid & 3;
        float s = 0.f, sq = 0.f;
        for (int i = 0; i < 64; i++) {
            float v = sA1[row * S1 + q * 64 + i];
            s += v; sq = fmaf(v, v, sq);
        }
        s  += __shfl_xor_sync(0xffffffffu, s, 1);  sq += __shfl_xor_sync(0xffffffffu, sq, 1);
        s  += __shfl_xor_sync(0xffffffffu, s, 2);  sq += __shfl_xor_sync(0xffffffffu, sq, 2);
        float mu = s * (1.0f / 256.0f);
        float var = sq * (1.0f / 256.0f) - mu * mu;
        float rs = rsqrtf(var + 1e-5f);
        for (int i = 0; i < 64; i++) {
            int sp = q * 64 + i;
            int lc = (sp & ~7) + ((sp & 1) << 2) + ((sp >> 1) & 3);   // inverse perm
            float v = sA1[row * S1 + sp];
            sA1[row * S1 + sp] = tf32r((v - mu) * rs * __ldg(ln_g + lc) + __ldg(ln_b + lc));
        }
    }
    __syncthreads();

    const int koff  = (lane & 3) << 1;
    const int rowA0 = wm * 16 + (lane >> 2);

    // ---- MLP1: N=256 (4 passes), K=256 (16 pairs), prefetched ----
    for (int p = 0; p < 4; p++) {
        const int nb  = p * 64 + wn * 32;
        const int ntb = nb >> 3;
        float C[4][4];
#pragma unroll
        for (int nt = 0; nt < 4; nt++)
#pragma unroll
            for (int e = 0; e < 4; e++) C[nt][e] = 0.f;
        const float* BP = g_W1p + (size_t)ntb * 2048 + lane * 4;
        uint4 b[4];
#pragma unroll
        for (int nt = 0; nt < 4; nt++) b[nt] = *(const uint4*)(BP + nt * 2048);
        for (int jj = 0; jj < 16; jj++) {
            const int jn = (jj < 15) ? jj + 1 : 15;
            uint4 bn[4];
#pragma unroll
            for (int nt = 0; nt < 4; nt++) bn[nt] = *(const uint4*)(BP + nt * 2048 + jn * 128);
            uint2 alo[2], ahi[2];
#pragma unroll
            for (int sub = 0; sub < 2; sub++) {
                const float* ap = sA1 + rowA0 * S1 + (jj * 2 + sub) * 8 + koff;
                alo[sub] = *(const uint2*)ap;
                ahi[sub] = *(const uint2*)(ap + 8 * S1);
            }
#pragma unroll
            for (int nt = 0; nt < 4; nt++) {
                mma8s(C[nt], alo[0].x, ahi[0].x, alo[0].y, ahi[0].y, b[nt].x, b[nt].y);
                mma8s(C[nt], alo[1].x, ahi[1].x, alo[1].y, ahi[1].y, b[nt].z, b[nt].w);
            }
#pragma unroll
            for (int nt = 0; nt < 4; nt++) b[nt] = bn[nt];
        }
#pragma unroll
        for (int nt = 0; nt < 4; nt++)
#pragma unroll
            for (int half = 0; half < 2; half++) {
                const int row = rowA0 + half * 8;
                const int j0  = nb + nt * 8 + koff;
#pragma unroll
                for (int e = 0; e < 2; e++) {
                    int j = j0 + e;
                    float f = fmaxf(C[nt][half * 2 + e] + __ldg(b1 + j), 0.0f);
                    sA2[row * S1 + (j & ~7) + ((j & 3) << 1) + ((j >> 2) & 1)] = tf32r(f);
                }
            }
    }
    __syncthreads();

    // ---- MLP2: N=128 (2 passes), K=256, prefetched ----
    for (int p = 0; p < 2; p++) {
        const int nb  = p * 64 + wn * 32;
        const int ntb = nb >> 3;
        float C[4][4];
#pragma unroll
        for (int nt = 0; nt < 4; nt++)
#pragma unroll
            for (int e = 0; e < 4; e++) C[nt][e] = 0.f;
        const float* BP = g_W2p + (size_t)ntb * 2048 + lane * 4;
        uint4 b[4];
#pragma unroll
        for (int nt = 0; nt < 4; nt++) b[nt] = *(const uint4*)(BP + nt * 2048);
        for (int jj = 0; jj < 16; jj++) {
            const int jn = (jj < 15) ? jj + 1 : 15;
            uint4 bn[4];
#pragma unroll
            for (int nt = 0; nt < 4; nt++) bn[nt] = *(const uint4*)(BP + nt * 2048 + jn * 128);
            uint2 alo[2], ahi[2];
#pragma unroll
            for (int sub = 0; sub < 2; sub++) {
                const float* ap = sA2 + rowA0 * S1 + (jj * 2 + sub) * 8 + koff;
                alo[sub] = *(const uint2*)ap;
                ahi[sub] = *(const uint2*)(ap + 8 * S1);
            }
#pragma unroll
            for (int nt = 0; nt < 4; nt++) {
                mma8s(C[nt], alo[0].x, ahi[0].x, alo[0].y, ahi[0].y, b[nt].x, b[nt].y);
                mma8s(C[nt], alo[1].x, ahi[1].x, alo[1].y, ahi[1].y, b[nt].z, b[nt].w);
            }
#pragma unroll
            for (int nt = 0; nt < 4; nt++) b[nt] = bn[nt];
        }
#pragma unroll
        for (int nt = 0; nt < 4; nt++)
#pragma unroll
            for (int half = 0; half < 2; half++) {
                const int row = rowA0 + half * 8;
                const int j0  = nb + nt * 8 + koff;
#pragma unroll
                for (int e = 0; e < 2; e++) {
                    int j = j0 + e;
                    float f = fmaxf(C[nt][half * 2 + e] + __ldg(b2 + j), 0.0f);
                    sA3[row * S3 + (j & ~7) + ((j & 3) << 1) + ((j >> 2) & 1)] = tf32r(f);
                }
            }
    }
    __syncthreads();

    // ---- MLP3: N=192 (3 passes), K=128 (8 pairs), prefetched ----
    for (int p = 0; p < 3; p++) {
        const int nb  = p * 64 + wn * 32;
        const int ntb = nb >> 3;
        float C[4][4];
#pragma unroll
        for (int nt = 0; nt < 4; nt++)
#pragma unroll
            for (int e = 0; e < 4; e++) C[nt][e] = 0.f;
        const float* BP = g_W3p + (size_t)ntb * 1024 + lane * 4;
        uint4 b[4];
#pragma unroll
        for (int nt = 0; nt < 4; nt++) b[nt] = *(const uint4*)(BP + nt * 1024);
        for (int jj = 0; jj < 8; jj++) {
            const int jn = (jj < 7) ? jj + 1 : 7;
            uint4 bn[4];
#pragma unroll
            for (int nt = 0; nt < 4; nt++) bn[nt] = *(const uint4*)(BP + nt * 1024 + jn * 128);
            uint2 alo[2], ahi[2];
#pragma unroll
            for (int sub = 0; sub < 2; sub++) {
                const float* ap = sA3 + rowA0 * S3 + (jj * 2 + sub) * 8 + koff;
                alo[sub] = *(const uint2*)ap;
                ahi[sub] = *(const uint2*)(ap + 8 * S3);
            }
#pragma unroll
            for (int nt = 0; nt < 4; nt++) {
                mma8s(C[nt], alo[0].x, ahi[0].x, alo[0].y, ahi[0].y, b[nt].x, b[nt].y);
                mma8s(C[nt], alo[1].x, ahi[1].x, alo[1].y, ahi[1].y, b[nt].z, b[nt].w);
            }
#pragma unroll
            for (int nt = 0; nt < 4; nt++) b[nt] = bn[nt];
        }
#pragma unroll
        for (int nt = 0; nt < 4; nt++)
#pragma unroll
            for (int half = 0; half < 2; half++) {
                const int row = rowA0 + half * 8;
                const int j0  = nb + nt * 8 + koff;
#pragma unroll
                for (int e = 0; e < 2; e++) {
                    int j = j0 + e;
                    if (j < 162) {
                        float kv = C[nt][half * 2 + e] + __ldg(b3 + j);
                        sA1[row * SKV + j] = fminf(fmaxf(kv, -3.0f), 3.0f);
                    }
                }
            }
    }
    __syncthreads();

    for (int t = tid; t < 384; t += 256) {
        const int row = t & 63, s = t >> 6;
        float corr = 0.f;
#pragma unroll
        for (int m = 0; m < 27; m++)
            corr = fmaf(sA1[row * SKV + s * 27 + m], sInn[row * 28 + m], corr);
        float xmv = g_xm[(size_t)(r0 + row) * 6 + s];
        out_x[(size_t)(r0 + row) * 6 + s] = fminf(fmaxf(xmv + corr, -5.0f), 5.0f);
    }
}

// ================= launch =================
extern "C" void kernel_launch(void* const* d_in, const int* in_sizes, int n_in,
                              void* d_out, int out_size)
{
    (void)in_sizes; (void)n_in; (void)out_size;
    const float* meas      = (const float*)d_in[0];
    const float* mask      = (const float*)d_in[1];
    const float* dtv       = (const float*)d_in[2];
    const float* baselines = (const float*)d_in[3];
    const float* x_prev    = (const float*)d_in[4];
    const float* hx        = (const float*)d_in[5];
    const float* W_ih      = (const float*)d_in[6];
    const float* W_hh      = (const float*)d_in[7];
    const float* b_ih      = (const float*)d_in[8];
    const float* b_hh      = (const float*)d_in[9];
    const float* ln_g      = (const float*)d_in[10];
    const float* ln_b      = (const float*)d_in[11];
    const float* W1        = (const float*)d_in[12];
    const float* b1        = (const float*)d_in[13];
    const float* W2        = (const float*)d_in[14];
    const float* b2        = (const float*)d_in[15];
    const float* W3        = (const float*)d_in[16];
    const float* b3        = (const float*)d_in[17];

    float* out   = (float*)d_out;
    float* out_x = out;                            // [B, 6]
    float* out_h = out + (size_t)B_TOTAL * 6;      // [B, 256]

    pack_kernel<<<(PACK_TOTAL + 255) / 256, 256>>>(W_ih, W_hh, b_ih, b_hh, W1, W2, W3);
    prep_kernel<<<B_TOTAL / 256, 256>>>(meas, mask, dtv, baselines, x_prev);

    cudaFuncSetAttribute(gru_kernel, cudaFuncAttributeMaxDynamicSharedMemorySize, G_SMEM);
    gru_kernel<<<B_TOTAL / 128, 256, G_SMEM>>>(hx, out_h);

    cudaFuncSetAttribute(mlp_kernel, cudaFuncAttributeMaxDynamicSharedMemorySize, M_SMEM);
    mlp_kernel<<<B_TOTAL / 64, 256, M_SMEM>>>(out_h, ln_g, ln_b, b1, b2, b3, out_x);
}

// round 9
// speedup vs baseline: 3.1593x; 1.6140x over previous
#include <cuda_runtime.h>
#include <cuda_fp16.h>
#include <stdint.h>
#include <math.h>

#define B_TOTAL   262144
#define IN_DIM    73
#define HID       256
#define PI_F      3.14159265358979323846f
#define NORM_R    (500.0f/150000.0f)

// ---- fp16 fragment-order packed weights (uint32 = half2 units) ----
// Region layout: [ntile][ksp][lane*4 + e], e = (ks16&1)*2 + reg
// value half2 = { W[n][kb], W[n][kb+1] }, n = ntile*8 + lane/4,
// kb = ks16*16 + reg*8 + (lane%4)*2, ks16 = ksp*2 + (e>>1)
#define WGU_R     0                // 32 ntiles x 11 ksp x 128 = 45056   (K=352: [ih|pad|hh])
#define WGU_Z     45056
#define WGU_GIN   90112            // 32 x 3 x 128 = 12288               (K=96)
#define WGU_GHN   102400           // 32 x 8 x 128 = 32768               (K=256)
#define WGU_TOTAL 135168

__device__ __align__(16) __half  g_ArnnH[(size_t)B_TOTAL * 96];   // perm16'd fp16 rnn_in
__device__ __align__(16) float   g_innov[(size_t)B_TOTAL * 27];
__device__ __align__(16) float   g_xm   [(size_t)B_TOTAL * 6];
__device__ __align__(16) uint32_t g_WgU [WGU_TOTAL];
__device__ __align__(16) float   g_bias [1024];
__device__ __align__(16) uint32_t g_W1U [32 * 8 * 128];           // 32768
__device__ __align__(16) uint32_t g_W2U [16 * 8 * 128];           // 16384
__device__ __align__(16) uint32_t g_W3U [24 * 4 * 128];           // 12288

// ---------------- helpers ----------------
// within-k16 permutation so each lane's 4 halves {2t,2t+1,2t+8,2t+9} are contiguous
__device__ __host__ __forceinline__ int perm16(int o) {
    return ((o & 6) >> 1) * 4 + ((o >> 3) << 1) + (o & 1);
}
__device__ __forceinline__ int invp16(int p) {
    return (p & 1) + ((p >> 2) & 3) * 2 + ((p >> 1) & 1) * 8;
}
__device__ __host__ __forceinline__ int a16(int k) {   // half-index within a row
    return ((k >> 4) << 4) + perm16(k & 15);
}
__device__ __forceinline__ void mma16(float* c, uint32_t a0, uint32_t a1, uint32_t a2,
                                      uint32_t a3, uint32_t b0, uint32_t b1) {
    asm volatile(
        "mma.sync.aligned.m16n8k16.row.col.f32.f16.f16.f32 "
        "{%0,%1,%2,%3}, {%4,%5,%6,%7}, {%8,%9}, {%0,%1,%2,%3};"
        : "+f"(c[0]), "+f"(c[1]), "+f"(c[2]), "+f"(c[3])
        : "r"(a0), "r"(a1), "r"(a2), "r"(a3), "r"(b0), "r"(b1));
}
__device__ __forceinline__ uint32_t pack2(float x, float y) {
    __half2 h = __floats2half2_rn(x, y);
    return *reinterpret_cast<uint32_t*>(&h);
}
__device__ __forceinline__ float sigm(float x) { return 1.0f / (1.0f + expf(-x)); }

// ================= K0: pack weights =================
__device__ __forceinline__ void frag16_decode(int i, int ksp_count, int& n, int& kb) {
    int per = ksp_count * 128;
    int ntile = i / per, rem = i - ntile * per;
    int ksp = rem >> 7, pos = rem & 127;
    int lane = pos >> 2, e = pos & 3;
    int ks16 = ksp * 2 + (e >> 1), reg = e & 1;
    n  = ntile * 8 + (lane >> 2);
    kb = ks16 * 16 + reg * 8 + (lane & 3) * 2;
}

__global__ void pack_kernel(const float* __restrict__ W_ih, const float* __restrict__ W_hh,
                            const float* __restrict__ b_ih, const float* __restrict__ b_hh,
                            const float* __restrict__ W1, const float* __restrict__ W2,
                            const float* __restrict__ W3) {
    int i = blockIdx.x * blockDim.x + threadIdx.x;
    if (i < 2 * 45056) {                       // r / z merged: K=352 [ih 0..72 | 0 | hh 96..351]
        int g = i / 45056, rem = i % 45056;
        int n, kb; frag16_decode(rem, 11, n, kb);
        int row = g * 256 + n;
        float v0 = 0.f, v1 = 0.f;
        if (kb < IN_DIM)          v0 = W_ih[(size_t)row * IN_DIM + kb];
        else if (kb >= 96)        v0 = W_hh[(size_t)row * HID + (kb - 96)];
        int k1 = kb + 1;
        if (k1 < IN_DIM)          v1 = W_ih[(size_t)row * IN_DIM + k1];
        else if (k1 >= 96)        v1 = W_hh[(size_t)row * HID + (k1 - 96)];
        g_WgU[(g ? WGU_Z : WGU_R) + rem] = pack2(v0, v1);
        return;
    }
    i -= 2 * 45056;
    if (i < 12288) {                           // gi_n: K=96
        int n, kb; frag16_decode(i, 3, n, kb);
        float v0 = (kb < IN_DIM)     ? W_ih[(size_t)(512 + n) * IN_DIM + kb]     : 0.f;
        float v1 = (kb + 1 < IN_DIM) ? W_ih[(size_t)(512 + n) * IN_DIM + kb + 1] : 0.f;
        g_WgU[WGU_GIN + i] = pack2(v0, v1);
        return;
    }
    i -= 12288;
    if (i < 32768) {                           // gh_n: K=256
        int n, kb; frag16_decode(i, 8, n, kb);
        g_WgU[WGU_GHN + i] = pack2(W_hh[(size_t)(512 + n) * HID + kb],
                                   W_hh[(size_t)(512 + n) * HID + kb + 1]);
        return;
    }
    i -= 32768;
    if (i < 1024) {
        int j = i & 255, t = i >> 8;
        float v;
        if (t == 0)      v = b_ih[j]       + b_hh[j];
        else if (t == 1) v = b_ih[256 + j] + b_hh[256 + j];
        else if (t == 2) v = b_ih[512 + j];
        else             v = b_hh[512 + j];
        g_bias[i] = v;
        return;
    }
    i -= 1024;
    if (i < 32768) {                           // W1: K=256, N=256
        int n, kb; frag16_decode(i, 8, n, kb);
        g_W1U[i] = pack2(W1[(size_t)n * 256 + kb], W1[(size_t)n * 256 + kb + 1]);
        return;
    }
    i -= 32768;
    if (i < 16384) {                           // W2: K=256, N=128
        int n, kb; frag16_decode(i, 8, n, kb);
        g_W2U[i] = pack2(W2[(size_t)n * 256 + kb], W2[(size_t)n * 256 + kb + 1]);
        return;
    }
    i -= 16384;
    if (i < 12288) {                           // W3: K=128, N=192 (zero-padded)
        int n, kb; frag16_decode(i, 4, n, kb);
        float v0 = (n < 162) ? W3[(size_t)n * 128 + kb]     : 0.f;
        float v1 = (n < 162) ? W3[(size_t)n * 128 + kb + 1] : 0.f;
        g_W3U[i] = pack2(v0, v1);
    }
}
#define PACK_TOTAL (2*45056 + 12288 + 32768 + 1024 + 32768 + 16384 + 12288)

// ================= K1: per-row prep =================
__global__ __launch_bounds__(256)
void prep_kernel(const float* __restrict__ meas, const float* __restrict__ mask,
                 const float* __restrict__ dt,   const float* __restrict__ baselines,
                 const float* __restrict__ x_prev) {
    size_t r = (size_t)blockIdx.x * blockDim.x + threadIdx.x;
    if (r >= B_TOTAL) return;
    float dtv = dt[r];
    float xp[6], bl[12];
#pragma unroll
    for (int i = 0; i < 6; i++)  xp[i] = x_prev[r * 6 + i];
#pragma unroll
    for (int i = 0; i < 12; i++) bl[i] = baselines[r * 12 + i];
    float ds = dtv * NORM_R;
    float xm[6];
    xm[0] = fmaf(ds, xp[1], xp[0]); xm[1] = xp[1];
    xm[2] = fmaf(ds, xp[3], xp[2]); xm[3] = xp[3];
    xm[4] = fmaf(ds, xp[5], xp[4]); xm[5] = xp[5];
#pragma unroll
    for (int i = 0; i < 6; i++) g_xm[r * 6 + i] = xm[i];

    float yp[27];
#pragma unroll
    for (int p = 0; p < 3; p++) {
        float x0 = xm[0], x2 = xm[2], x4 = xm[4];
        if (p == 1) { x0 -= bl[0]; x2 -= bl[2]; x4 -= bl[4]; }
        if (p == 2) { x0 -= bl[6]; x2 -= bl[8]; x4 -= bl[10]; }
        float rxy = sqrtf(x0 * x0 + x2 * x2 + 1e-9f);
        float az  = atan2f(x2, x0) * (1.0f / PI_F);
        float el  = atan2f(x4, rxy) * (1.0f / PI_F);
        float rr  = sqrtf(x0 * x0 + x2 * x2 + x4 * x4 + 1e-9f);
        yp[p*9+0] = az; yp[p*9+1] = el; yp[p*9+2] = rr;
        yp[p*9+3] = az; yp[p*9+4] = el; yp[p*9+5] = 0.0f;
        yp[p*9+6] = az; yp[p*9+7] = 0.0f; yp[p*9+8] = 0.0f;
    }
    __half* A = g_ArnnH + r * 96;
#pragma unroll
    for (int m = 0; m < 27; m++) {
        float mv = meas[r * 27 + m];
        float mk = mask[r * 27 + m];
        float in = mv - yp[m];
        int mm = m % 9;
        bool ang = (mm == 0) | (mm == 1) | (mm == 3) | (mm == 4) | (mm == 6);
        if (ang) in = in - 2.0f * rintf(in * 0.5f);
        in *= mk;
        g_innov[r * 27 + m] = in;
        A[a16(m)]      = __float2half_rn(in);
        A[a16(27 + m)] = __float2half_rn(mk);
    }
    A[a16(54)] = __float2half_rn(dtv);
#pragma unroll
    for (int i = 0; i < 6; i++)  A[a16(55 + i)] = __float2half_rn(xm[i]);
#pragma unroll
    for (int i = 0; i < 12; i++) A[a16(61 + i)] = __float2half_rn(bl[i]);
#pragma unroll
    for (int i = 73; i < 96; i++) A[a16(i)] = __float2half_rn(0.0f);
}

// ================= K2: GRU (M=128/CTA, warps 2 rows x 4 cols) =================
#define GSH 368                                   // halves per A row (368/2=184, 184%32=24: conflict-free)
#define G_SMEM (128 * GSH * 2 + 4096)

__global__ __launch_bounds__(256, 1)
void gru_kernel(const float* __restrict__ hx, float* __restrict__ out_h) {
    extern __shared__ char smc[];
    __half* sAh   = (__half*)smc;                 // [128][GSH]: rnn halves 0..95, hx 96..351
    float*  sBias = (float*)(smc + 128 * GSH * 2);
    const int tid = threadIdx.x, lane = tid & 31, wid = tid >> 5;
    const int wn = wid & 3, wm = wid >> 2;        // wm in {0,1}: 64 rows; wn in {0..3}: 16 cols
    const int g = lane >> 2, tig = lane & 3;
    const int r0 = blockIdx.x * 128;

    // stage rnn halves (already perm16'd in gmem)
    for (int t = tid; t < 128 * 12; t += 256) {
        int row = t / 12, c = t % 12;
        ((uint4*)(sAh + row * GSH))[c] =
            ((const uint4*)(g_ArnnH + (size_t)(r0 + row) * 96))[c];
    }
    // stage hx -> fp16 perm16 at halves 96..351
    for (int t = tid; t < 128 * 64; t += 256) {
        int row = t >> 6, kq = (t & 63) << 2;
        float4 v = *(const float4*)(hx + (size_t)(r0 + row) * HID + kq);
        int base = row * GSH + 96 + ((kq >> 4) << 4) + perm16(kq & 15);
        *(uint32_t*)(sAh + base)     = pack2(v.x, v.y);
        *(uint32_t*)(sAh + base + 4) = pack2(v.z, v.w);
    }
    for (int t = tid; t < 1024; t += 256) sBias[t] = g_bias[t];
    __syncthreads();

    const int rowW = wm * 64 + g;

    for (int pass = 0; pass < 4; pass++) {
        const int jb  = pass * 64 + wn * 16;
        const int ntb = jb >> 3;                  // 2 ntiles per warp
        float Cr[4][2][4], Cz[4][2][4], Cn[4][2][4], Ch[4][2][4];
#pragma unroll
        for (int mt = 0; mt < 4; mt++)
#pragma unroll
            for (int nt = 0; nt < 2; nt++)
#pragma unroll
                for (int e = 0; e < 4; e++) {
                    Cr[mt][nt][e] = 0.f; Cz[mt][nt][e] = 0.f;
                    Cn[mt][nt][e] = 0.f; Ch[mt][nt][e] = 0.f;
                }

        const uint32_t* BrP = g_WgU + WGU_R   + ntb * 1408 + lane * 4;   // 11*128
        const uint32_t* BzP = g_WgU + WGU_Z   + ntb * 1408 + lane * 4;
        const uint32_t* BiP = g_WgU + WGU_GIN + ntb * 384  + lane * 4;   // 3*128
        const uint32_t* BhP = g_WgU + WGU_GHN + ntb * 1024 + lane * 4;   // 8*128

        // ---- r & z : K=352 (11 ksp = k32 steps), prefetched ----
        {
            uint4 br[2], bz[2];
#pragma unroll
            for (int nt = 0; nt < 2; nt++) {
                br[nt] = *(const uint4*)(BrP + nt * 1408);
                bz[nt] = *(const uint4*)(BzP + nt * 1408);
            }
            for (int ksp = 0; ksp < 11; ksp++) {
                const int jn = (ksp < 10) ? ksp + 1 : 10;
                uint4 brn[2], bzn[2];
#pragma unroll
                for (int nt = 0; nt < 2; nt++) {
                    brn[nt] = *(const uint4*)(BrP + nt * 1408 + jn * 128);
                    bzn[nt] = *(const uint4*)(BzP + nt * 1408 + jn * 128);
                }
                uint2 lo[2][4], hi[2][4];
#pragma unroll
                for (int sub = 0; sub < 2; sub++)
#pragma unroll
                    for (int mt = 0; mt < 4; mt++) {
                        const __half* ap = sAh + (rowW + mt * 16) * GSH
                                         + (ksp * 2 + sub) * 16 + tig * 4;
                        lo[sub][mt] = *(const uint2*)ap;
                        hi[sub][mt] = *(const uint2*)(ap + 8 * GSH);
                    }
#pragma unroll
                for (int nt = 0; nt < 2; nt++)
#pragma unroll
                    for (int mt = 0; mt < 4; mt++) {
                        mma16(Cr[mt][nt], lo[0][mt].x, hi[0][mt].x, lo[0][mt].y, hi[0][mt].y, br[nt].x, br[nt].y);
                        mma16(Cr[mt][nt], lo[1][mt].x, hi[1][mt].x, lo[1][mt].y, hi[1][mt].y, br[nt].z, br[nt].w);
                        mma16(Cz[mt][nt], lo[0][mt].x, hi[0][mt].x, lo[0][mt].y, hi[0][mt].y, bz[nt].x, bz[nt].y);
                        mma16(Cz[mt][nt], lo[1][mt].x, hi[1][mt].x, lo[1][mt].y, hi[1][mt].y, bz[nt].z, bz[nt].w);
                    }
#pragma unroll
                for (int nt = 0; nt < 2; nt++) { br[nt] = brn[nt]; bz[nt] = bzn[nt]; }
            }
        }
        // ---- gi_n : K=96 (3 ksp), A blocks 0..5 ----
        {
            uint4 bi[2];
#pragma unroll
            for (int nt = 0; nt < 2; nt++) bi[nt] = *(const uint4*)(BiP + nt * 384);
            for (int ksp = 0; ksp < 3; ksp++) {
                const int jn = (ksp < 2) ? ksp + 1 : 2;
                uint4 bin[2];
#pragma unroll
                for (int nt = 0; nt < 2; nt++)
                    bin[nt] = *(const uint4*)(BiP + nt * 384 + jn * 128);
                uint2 lo[2][4], hi[2][4];
#pragma unroll
                for (int sub = 0; sub < 2; sub++)
#pragma unroll
                    for (int mt = 0; mt < 4; mt++) {
                        const __half* ap = sAh + (rowW + mt * 16) * GSH
                                         + (ksp * 2 + sub) * 16 + tig * 4;
                        lo[sub][mt] = *(const uint2*)ap;
                        hi[sub][mt] = *(const uint2*)(ap + 8 * GSH);
                    }
#pragma unroll
                for (int nt = 0; nt < 2; nt++)
#pragma unroll
                    for (int mt = 0; mt < 4; mt++) {
                        mma16(Cn[mt][nt], lo[0][mt].x, hi[0][mt].x, lo[0][mt].y, hi[0][mt].y, bi[nt].x, bi[nt].y);
                        mma16(Cn[mt][nt], lo[1][mt].x, hi[1][mt].x, lo[1][mt].y, hi[1][mt].y, bi[nt].z, bi[nt].w);
                    }
#pragma unroll
                for (int nt = 0; nt < 2; nt++) bi[nt] = bin[nt];
            }
        }
        // ---- gh_n : K=256 (8 ksp), A blocks 6..21 ----
        {
            uint4 bh[2];
#pragma unroll
            for (int nt = 0; nt < 2; nt++) bh[nt] = *(const uint4*)(BhP + nt * 1024);
            for (int ksp = 0; ksp < 8; ksp++) {
                const int jn = (ksp < 7) ? ksp + 1 : 7;
                uint4 bhn[2];
#pragma unroll
                for (int nt = 0; nt < 2; nt++)
                    bhn[nt] = *(const uint4*)(BhP + nt * 1024 + jn * 128);
                uint2 lo[2][4], hi[2][4];
#pragma unroll
                for (int sub = 0; sub < 2; sub++)
#pragma unroll
                    for (int mt = 0; mt < 4; mt++) {
                        const __half* ap = sAh + (rowW + mt * 16) * GSH
                                         + (6 + ksp * 2 + sub) * 16 + tig * 4;
                        lo[sub][mt] = *(const uint2*)ap;
                        hi[sub][mt] = *(const uint2*)(ap + 8 * GSH);
                    }
#pragma unroll
                for (int nt = 0; nt < 2; nt++)
#pragma unroll
                    for (int mt = 0; mt < 4; mt++) {
                        mma16(Ch[mt][nt], lo[0][mt].x, hi[0][mt].x, lo[0][mt].y, hi[0][mt].y, bh[nt].x, bh[nt].y);
                        mma16(Ch[mt][nt], lo[1][mt].x, hi[1][mt].x, lo[1][mt].y, hi[1][mt].y, bh[nt].z, bh[nt].w);
                    }
#pragma unroll
                for (int nt = 0; nt < 2; nt++) bh[nt] = bhn[nt];
            }
        }
        // ---- epilogue ----
#pragma unroll
        for (int mt = 0; mt < 4; mt++)
#pragma unroll
            for (int nt = 0; nt < 2; nt++)
#pragma unroll
                for (int hh = 0; hh < 2; hh++) {
                    const int row = rowW + mt * 16 + hh * 8;
                    const int jc  = jb + nt * 8 + tig * 2;
                    float h2[2];
#pragma unroll
                    for (int e = 0; e < 2; e++) {
                        const int j = jc + e;
                        const int idx = hh * 2 + e;
                        float rg = sigm(Cr[mt][nt][idx] + sBias[j]);
                        float zg = sigm(Cz[mt][nt][idx] + sBias[256 + j]);
                        float nn = tanhf(Cn[mt][nt][idx] + sBias[512 + j]
                                         + rg * (Ch[mt][nt][idx] + sBias[768 + j]));
                        float hxv = __half2float(sAh[row * GSH + 96 + a16(j)]);
                        h2[e] = (1.0f - zg) * nn + zg * hxv;
                    }
                    *(float2*)(out_h + (size_t)(r0 + row) * HID + jc) = make_float2(h2[0], h2[1]);
                }
    }
}

// ================= K3: LN + MLP + gain head (M=64/CTA, 2 CTAs/SM) =================
#define KS1 272                                   // 272/2=136, 136%32=8: conflict-free
#define KS3 144                                   // 72%32=8: conflict-free
#define SKV 200
#define M_SMEM (64*KS1*2*2 + 64*KS3*2 + 64*28*4)  // sA1h, sA2h, sA3h, sInn = 95232

__global__ __launch_bounds__(256, 2)
void mlp_kernel(const float* __restrict__ h_in,
                const float* __restrict__ ln_g, const float* __restrict__ ln_b,
                const float* __restrict__ b1, const float* __restrict__ b2,
                const float* __restrict__ b3, float* __restrict__ out_x) {
    extern __shared__ char smc[];
    __half* sA1h = (__half*)smc;                       // [64][KS1]
    __half* sA2h = sA1h + 64 * KS1;                    // [64][KS1]
    __half* sA3h = sA2h + 64 * KS1;                    // [64][KS3]
    float*  sInn = (float*)(smc + 64 * KS1 * 2 * 2 + 64 * KS3 * 2);  // [64][28]
    float*  sKV  = (float*)smc;                        // [64][SKV], overlays sA1h/sA2h (dead by MLP3)
    const int tid = threadIdx.x, lane = tid & 31, wid = tid >> 5;
    const int wn = wid & 3, wm = wid >> 2;             // wm {0,1}: 32 rows; wn {0..3}: 16 cols
    const int g = lane >> 2, tig = lane & 3;
    const int r0 = blockIdx.x * 64;

    // stage h -> fp16 perm16
    for (int t = tid; t < 64 * 64; t += 256) {
        int row = t >> 6, kq = (t & 63) << 2;
        float4 v = *(const float4*)(h_in + (size_t)(r0 + row) * HID + kq);
        int base = row * KS1 + ((kq >> 4) << 4) + perm16(kq & 15);
        *(uint32_t*)(sA1h + base)     = pack2(v.x, v.y);
        *(uint32_t*)(sA1h + base + 4) = pack2(v.z, v.w);
    }
    for (int t = tid; t < 64 * 27; t += 256) {
        int row = t / 27, m = t % 27;
        sInn[row * 28 + m] = g_innov[(size_t)(r0 + row) * 27 + m];
    }
    __syncthreads();

    // LayerNorm on fp16 tile (stats in fp32)
    {
        const int row = tid >> 2, q = tid & 3;
        float s = 0.f, sq = 0.f;
        for (int i = 0; i < 64; i++) {
            float v = __half2float(sA1h[row * KS1 + q * 64 + i]);
            s += v; sq = fmaf(v, v, sq);
        }
        s  += __shfl_xor_sync(0xffffffffu, s, 1);  sq += __shfl_xor_sync(0xffffffffu, sq, 1);
        s  += __shfl_xor_sync(0xffffffffu, s, 2);  sq += __shfl_xor_sync(0xffffffffu, sq, 2);
        float mu = s * (1.0f / 256.0f);
        float var = sq * (1.0f / 256.0f) - mu * mu;
        float rs = rsqrtf(var + 1e-5f);
        for (int i = 0; i < 64; i++) {
            int p = q * 64 + i;
            int k = ((p >> 4) << 4) + invp16(p & 15);
            float v = __half2float(sA1h[row * KS1 + p]);
            sA1h[row * KS1 + p] =
                __float2half_rn((v - mu) * rs * __ldg(ln_g + k) + __ldg(ln_b + k));
        }
    }
    __syncthreads();

    const int rowW = wm * 32 + g;

    // ---- MLP1: N=256 (4 passes), K=256 (8 ksp), prefetched ----
    for (int p = 0; p < 4; p++) {
        const int nb  = p * 64 + wn * 16;
        const int ntb = nb >> 3;
        float C[2][2][4];
#pragma unroll
        for (int mt = 0; mt < 2; mt++)
#pragma unroll
            for (int nt = 0; nt < 2; nt++)
#pragma unroll
                for (int e = 0; e < 4; e++) C[mt][nt][e] = 0.f;
        const uint32_t* BP = g_W1U + ntb * 1024 + lane * 4;
        uint4 b[2];
#pragma unroll
        for (int nt = 0; nt < 2; nt++) b[nt] = *(const uint4*)(BP + nt * 1024);
        for (int ksp = 0; ksp < 8; ksp++) {
            const int jn = (ksp < 7) ? ksp + 1 : 7;
            uint4 bn[2];
#pragma unroll
            for (int nt = 0; nt < 2; nt++) bn[nt] = *(const uint4*)(BP + nt * 1024 + jn * 128);
            uint2 lo[2][2], hi[2][2];
#pragma unroll
            for (int sub = 0; sub < 2; sub++)
#pragma unroll
                for (int mt = 0; mt < 2; mt++) {
                    const __half* ap = sA1h + (rowW + mt * 16) * KS1
                                     + (ksp * 2 + sub) * 16 + tig * 4;
                    lo[sub][mt] = *(const uint2*)ap;
                    hi[sub][mt] = *(const uint2*)(ap + 8 * KS1);
                }
#pragma unroll
            for (int nt = 0; nt < 2; nt++)
#pragma unroll
                for (int mt = 0; mt < 2; mt++) {
                    mma16(C[mt][nt], lo[0][mt].x, hi[0][mt].x, lo[0][mt].y, hi[0][mt].y, b[nt].x, b[nt].y);
                    mma16(C[mt][nt], lo[1][mt].x, hi[1][mt].x, lo[1][mt].y, hi[1][mt].y, b[nt].z, b[nt].w);
                }
#pragma unroll
            for (int nt = 0; nt < 2; nt++) b[nt] = bn[nt];
        }
#pragma unroll
        for (int mt = 0; mt < 2; mt++)
#pragma unroll
            for (int nt = 0; nt < 2; nt++)
#pragma unroll
                for (int hh = 0; hh < 2; hh++) {
                    const int row = rowW + mt * 16 + hh * 8;
                    const int j   = nb + nt * 8 + tig * 2;
                    float f0 = fmaxf(C[mt][nt][hh * 2 + 0] + __ldg(b1 + j),     0.0f);
                    float f1 = fmaxf(C[mt][nt][hh * 2 + 1] + __ldg(b1 + j + 1), 0.0f);
                    int pos = row * KS1 + ((j >> 4) << 4) + perm16(j & 15);
                    *(uint32_t*)(sA2h + pos) = pack2(f0, f1);
                }
    }
    __syncthreads();

    // ---- MLP2: N=128 (2 passes), K=256 ----
    for (int p = 0; p < 2; p++) {
        const int nb  = p * 64 + wn * 16;
        const int ntb = nb >> 3;
        float C[2][2][4];
#pragma unroll
        for (int mt = 0; mt < 2; mt++)
#pragma unroll
            for (int nt = 0; nt < 2; nt++)
#pragma unroll
                for (int e = 0; e < 4; e++) C[mt][nt][e] = 0.f;
        const uint32_t* BP = g_W2U + ntb * 1024 + lane * 4;
        uint4 b[2];
#pragma unroll
        for (int nt = 0; nt < 2; nt++) b[nt] = *(const uint4*)(BP + nt * 1024);
        for (int ksp = 0; ksp < 8; ksp++) {
            const int jn = (ksp < 7) ? ksp + 1 : 7;
            uint4 bn[2];
#pragma unroll
            for (int nt = 0; nt < 2; nt++) bn[nt] = *(const uint4*)(BP + nt * 1024 + jn * 128);
            uint2 lo[2][2], hi[2][2];
#pragma unroll
            for (int sub = 0; sub < 2; sub++)
#pragma unroll
                for (int mt = 0; mt < 2; mt++) {
                    const __half* ap = sA2h + (rowW + mt * 16) * KS1
                                     + (ksp * 2 + sub) * 16 + tig * 4;
                    lo[sub][mt] = *(const uint2*)ap;
                    hi[sub][mt] = *(const uint2*)(ap + 8 * KS1);
                }
#pragma unroll
            for (int nt = 0; nt < 2; nt++)
#pragma unroll
                for (int mt = 0; mt < 2; mt++) {
                    mma16(C[mt][nt], lo[0][mt].x, hi[0][mt].x, lo[0][mt].y, hi[0][mt].y, b[nt].x, b[nt].y);
                    mma16(C[mt][nt], lo[1][mt].x, hi[1][mt].x, lo[1][mt].y, hi[1][mt].y, b[nt].z, b[nt].w);
                }
#pragma unroll
            for (int nt = 0; nt < 2; nt++) b[nt] = bn[nt];
        }
#pragma unroll
        for (int mt = 0; mt < 2; mt++)
#pragma unroll
            for (int nt = 0; nt < 2; nt++)
#pragma unroll
                for (int hh = 0; hh < 2; hh++) {
                    const int row = rowW + mt * 16 + hh * 8;
                    const int j   = nb + nt * 8 + tig * 2;
                    float f0 = fmaxf(C[mt][nt][hh * 2 + 0] + __ldg(b2 + j),     0.0f);
                    float f1 = fmaxf(C[mt][nt][hh * 2 + 1] + __ldg(b2 + j + 1), 0.0f);
                    int pos = row * KS3 + ((j >> 4) << 4) + perm16(j & 15);
                    *(uint32_t*)(sA3h + pos) = pack2(f0, f1);
                }
    }
    __syncthreads();

    // ---- MLP3: N=192 (3 passes), K=128 (4 ksp); kv -> sKV (overlays dead sA1/sA2) ----
    for (int p = 0; p < 3; p++) {
        const int nb  = p * 64 + wn * 16;
        const int ntb = nb >> 3;
        float C[2][2][4];
#pragma unroll
        for (int mt = 0; mt < 2; mt++)
#pragma unroll
            for (int nt = 0; nt < 2; nt++)
#pragma unroll
                for (int e = 0; e < 4; e++) C[mt][nt][e] = 0.f;
        const uint32_t* BP = g_W3U + ntb * 512 + lane * 4;
        uint4 b[2];
#pragma unroll
        for (int nt = 0; nt < 2; nt++) b[nt] = *(const uint4*)(BP + nt * 512);
        for (int ksp = 0; ksp < 4; ksp++) {
            const int jn = (ksp < 3) ? ksp + 1 : 3;
            uint4 bn[2];
#pragma unroll
            for (int nt = 0; nt < 2; nt++) bn[nt] = *(const uint4*)(BP + nt * 512 + jn * 128);
            uint2 lo[2][2], hi[2][2];
#pragma unroll
            for (int sub = 0; sub < 2; sub++)
#pragma unroll
                for (int mt = 0; mt < 2; mt++) {
                    const __half* ap = sA3h + (rowW + mt * 16) * KS3
                                     + (ksp * 2 + sub) * 16 + tig * 4;
                    lo[sub][mt] = *(const uint2*)ap;
                    hi[sub][mt] = *(const uint2*)(ap + 8 * KS3);
                }
#pragma unroll
            for (int nt = 0; nt < 2; nt++)
#pragma unroll
                for (int mt = 0; mt < 2; mt++) {
                    mma16(C[mt][nt], lo[0][mt].x, hi[0][mt].x, lo[0][mt].y, hi[0][mt].y, b[nt].x, b[nt].y);
                    mma16(C[mt][nt], lo[1][mt].x, hi[1][mt].x, lo[1][mt].y, hi[1][mt].y, b[nt].z, b[nt].w);
                }
#pragma unroll
            for (int nt = 0; nt < 2; nt++) b[nt] = bn[nt];
        }
#pragma unroll
        for (int mt = 0; mt < 2; mt++)
#pragma unroll
            for (int nt = 0; nt < 2; nt++)
#pragma unroll
                for (int hh = 0; hh < 2; hh++) {
                    const int row = rowW + mt * 16 + hh * 8;
                    const int j0  = nb + nt * 8 + tig * 2;
#pragma unroll
                    for (int e = 0; e < 2; e++) {
                        int j = j0 + e;
                        if (j < 162) {
                            float kv = C[mt][nt][hh * 2 + e] + __ldg(b3 + j);
                            sKV[row * SKV + j] = fminf(fmaxf(kv, -3.0f), 3.0f);
                        }
                    }
                }
    }
    __syncthreads();

    // ---- correction + clamp ----
    for (int t = tid; t < 384; t += 256) {
        const int row = t & 63, s = t >> 6;
        float corr = 0.f;
#pragma unroll
        for (int m = 0; m < 27; m++)
            corr = fmaf(sKV[row * SKV + s * 27 + m], sInn[row * 28 + m], corr);
        float xmv = g_xm[(size_t)(r0 + row) * 6 + s];
        out_x[(size_t)(r0 + row) * 6 + s] = fminf(fmaxf(xmv + corr, -5.0f), 5.0f);
    }
}

// ================= launch =================
extern "C" void kernel_launch(void* const* d_in, const int* in_sizes, int n_in,
                              void* d_out, int out_size)
{
    (void)in_sizes; (void)n_in; (void)out_size;
    const float* meas      = (const float*)d_in[0];
    const float* mask      = (const float*)d_in[1];
    const float* dtv       = (const float*)d_in[2];
    const float* baselines = (const float*)d_in[3];
    const float* x_prev    = (const float*)d_in[4];
    const float* hx        = (const float*)d_in[5];
    const float* W_ih      = (const float*)d_in[6];
    const float* W_hh      = (const float*)d_in[7];
    const float* b_ih      = (const float*)d_in[8];
    const float* b_hh      = (const float*)d_in[9];
    const float* ln_g      = (const float*)d_in[10];
    const float* ln_b      = (const float*)d_in[11];
    const float* W1        = (const float*)d_in[12];
    const float* b1        = (const float*)d_in[13];
    const float* W2        = (const float*)d_in[14];
    const float* b2        = (const float*)d_in[15];
    const float* W3        = (const float*)d_in[16];
    const float* b3        = (const float*)d_in[17];

    float* out   = (float*)d_out;
    float* out_x = out;                            // [B, 6]
    float* out_h = out + (size_t)B_TOTAL * 6;      // [B, 256]

    pack_kernel<<<(PACK_TOTAL + 255) / 256, 256>>>(W_ih, W_hh, b_ih, b_hh, W1, W2, W3);
    prep_kernel<<<B_TOTAL / 256, 256>>>(meas, mask, dtv, baselines, x_prev);

    cudaFuncSetAttribute(gru_kernel, cudaFuncAttributeMaxDynamicSharedMemorySize, G_SMEM);
    gru_kernel<<<B_TOTAL / 128, 256, G_SMEM>>>(hx, out_h);

    cudaFuncSetAttribute(mlp_kernel, cudaFuncAttributeMaxDynamicSharedMemorySize, M_SMEM);
    mlp_kernel<<<B_TOTAL / 64, 256, M_SMEM>>>(out_h, ln_g, ln_b, b1, b2, b3, out_x);
}

// round 10
// speedup vs baseline: 3.2643x; 1.0332x over previous
#include <cuda_runtime.h>
#include <cuda_fp16.h>
#include <stdint.h>
#include <math.h>

#define B_TOTAL   262144
#define IN_DIM    73
#define HID       256
#define PI_F      3.14159265358979323846f
#define NORM_R    (500.0f/150000.0f)

// ---- fp16 fragment-order packed weights (uint32 = half2 units) ----
#define WGU_R     0                // 32 ntiles x 11 ksp x 128 = 45056   (K=352: [ih|pad|hh])
#define WGU_Z     45056
#define WGU_GIN   90112            // 32 x 3 x 128 = 12288               (K=96)
#define WGU_GHN   102400           // 32 x 8 x 128 = 32768               (K=256)
#define WGU_TOTAL 135168

__device__ __align__(16) __half  g_ArnnH[(size_t)B_TOTAL * 96];   // perm16'd fp16 rnn_in
__device__ __align__(16) float   g_innov[(size_t)B_TOTAL * 27];
__device__ __align__(16) float   g_xm   [(size_t)B_TOTAL * 6];
__device__ __align__(16) uint32_t g_WgU [WGU_TOTAL];
__device__ __align__(16) float   g_bias [1024];
__device__ __align__(16) uint32_t g_W1U [32 * 8 * 128];           // 32768
__device__ __align__(16) uint32_t g_W2U [16 * 8 * 128];           // 16384
__device__ __align__(16) uint32_t g_W3U [24 * 4 * 128];           // 12288

// ---------------- helpers ----------------
__device__ __host__ __forceinline__ int perm16(int o) {
    return ((o & 6) >> 1) * 4 + ((o >> 3) << 1) + (o & 1);
}
__device__ __forceinline__ int invp16(int p) {
    return (p & 1) + ((p >> 2) & 3) * 2 + ((p >> 1) & 1) * 8;
}
__device__ __host__ __forceinline__ int a16(int k) {
    return ((k >> 4) << 4) + perm16(k & 15);
}
__device__ __forceinline__ void mma16(float* c, uint32_t a0, uint32_t a1, uint32_t a2,
                                      uint32_t a3, uint32_t b0, uint32_t b1) {
    asm volatile(
        "mma.sync.aligned.m16n8k16.row.col.f32.f16.f16.f32 "
        "{%0,%1,%2,%3}, {%4,%5,%6,%7}, {%8,%9}, {%0,%1,%2,%3};"
        : "+f"(c[0]), "+f"(c[1]), "+f"(c[2]), "+f"(c[3])
        : "r"(a0), "r"(a1), "r"(a2), "r"(a3), "r"(b0), "r"(b1));
}
__device__ __forceinline__ uint32_t pack2(float x, float y) {
    __half2 h = __floats2half2_rn(x, y);
    return *reinterpret_cast<uint32_t*>(&h);
}
__device__ __forceinline__ float sigm(float x) { return 1.0f / (1.0f + expf(-x)); }

// ================= K0: pack weights =================
__device__ __forceinline__ void frag16_decode(int i, int ksp_count, int& n, int& kb) {
    int per = ksp_count * 128;
    int ntile = i / per, rem = i - ntile * per;
    int ksp = rem >> 7, pos = rem & 127;
    int lane = pos >> 2, e = pos & 3;
    int ks16 = ksp * 2 + (e >> 1), reg = e & 1;
    n  = ntile * 8 + (lane >> 2);
    kb = ks16 * 16 + reg * 8 + (lane & 3) * 2;
}

__global__ void pack_kernel(const float* __restrict__ W_ih, const float* __restrict__ W_hh,
                            const float* __restrict__ b_ih, const float* __restrict__ b_hh,
                            const float* __restrict__ W1, const float* __restrict__ W2,
                            const float* __restrict__ W3) {
    int i = blockIdx.x * blockDim.x + threadIdx.x;
    if (i < 2 * 45056) {                       // r / z merged: K=352 [ih 0..72 | 0 | hh 96..351]
        int g = i / 45056, rem = i % 45056;
        int n, kb; frag16_decode(rem, 11, n, kb);
        int row = g * 256 + n;
        float v0 = 0.f, v1 = 0.f;
        if (kb < IN_DIM)          v0 = W_ih[(size_t)row * IN_DIM + kb];
        else if (kb >= 96)        v0 = W_hh[(size_t)row * HID + (kb - 96)];
        int k1 = kb + 1;
        if (k1 < IN_DIM)          v1 = W_ih[(size_t)row * IN_DIM + k1];
        else if (k1 >= 96)        v1 = W_hh[(size_t)row * HID + (k1 - 96)];
        g_WgU[(g ? WGU_Z : WGU_R) + rem] = pack2(v0, v1);
        return;
    }
    i -= 2 * 45056;
    if (i < 12288) {                           // gi_n: K=96
        int n, kb; frag16_decode(i, 3, n, kb);
        float v0 = (kb < IN_DIM)     ? W_ih[(size_t)(512 + n) * IN_DIM + kb]     : 0.f;
        float v1 = (kb + 1 < IN_DIM) ? W_ih[(size_t)(512 + n) * IN_DIM + kb + 1] : 0.f;
        g_WgU[WGU_GIN + i] = pack2(v0, v1);
        return;
    }
    i -= 12288;
    if (i < 32768) {                           // gh_n: K=256
        int n, kb; frag16_decode(i, 8, n, kb);
        g_WgU[WGU_GHN + i] = pack2(W_hh[(size_t)(512 + n) * HID + kb],
                                   W_hh[(size_t)(512 + n) * HID + kb + 1]);
        return;
    }
    i -= 32768;
    if (i < 1024) {
        int j = i & 255, t = i >> 8;
        float v;
        if (t == 0)      v = b_ih[j]       + b_hh[j];
        else if (t == 1) v = b_ih[256 + j] + b_hh[256 + j];
        else if (t == 2) v = b_ih[512 + j];
        else             v = b_hh[512 + j];
        g_bias[i] = v;
        return;
    }
    i -= 1024;
    if (i < 32768) {                           // W1: K=256, N=256
        int n, kb; frag16_decode(i, 8, n, kb);
        g_W1U[i] = pack2(W1[(size_t)n * 256 + kb], W1[(size_t)n * 256 + kb + 1]);
        return;
    }
    i -= 32768;
    if (i < 16384) {                           // W2: K=256, N=128
        int n, kb; frag16_decode(i, 8, n, kb);
        g_W2U[i] = pack2(W2[(size_t)n * 256 + kb], W2[(size_t)n * 256 + kb + 1]);
        return;
    }
    i -= 16384;
    if (i < 12288) {                           // W3: K=128, N=192 (zero-padded)
        int n, kb; frag16_decode(i, 4, n, kb);
        float v0 = (n < 162) ? W3[(size_t)n * 128 + kb]     : 0.f;
        float v1 = (n < 162) ? W3[(size_t)n * 128 + kb + 1] : 0.f;
        g_W3U[i] = pack2(v0, v1);
    }
}
#define PACK_TOTAL (2*45056 + 12288 + 32768 + 1024 + 32768 + 16384 + 12288)

// ================= K1: per-row prep =================
__global__ __launch_bounds__(256)
void prep_kernel(const float* __restrict__ meas, const float* __restrict__ mask,
                 const float* __restrict__ dt,   const float* __restrict__ baselines,
                 const float* __restrict__ x_prev) {
    size_t r = (size_t)blockIdx.x * blockDim.x + threadIdx.x;
    if (r >= B_TOTAL) return;
    float dtv = dt[r];
    float xp[6], bl[12];
#pragma unroll
    for (int i = 0; i < 6; i++)  xp[i] = x_prev[r * 6 + i];
#pragma unroll
    for (int i = 0; i < 12; i++) bl[i] = baselines[r * 12 + i];
    float ds = dtv * NORM_R;
    float xm[6];
    xm[0] = fmaf(ds, xp[1], xp[0]); xm[1] = xp[1];
    xm[2] = fmaf(ds, xp[3], xp[2]); xm[3] = xp[3];
    xm[4] = fmaf(ds, xp[5], xp[4]); xm[5] = xp[5];
#pragma unroll
    for (int i = 0; i < 6; i++) g_xm[r * 6 + i] = xm[i];

    float yp[27];
#pragma unroll
    for (int p = 0; p < 3; p++) {
        float x0 = xm[0], x2 = xm[2], x4 = xm[4];
        if (p == 1) { x0 -= bl[0]; x2 -= bl[2]; x4 -= bl[4]; }
        if (p == 2) { x0 -= bl[6]; x2 -= bl[8]; x4 -= bl[10]; }
        float rxy = sqrtf(x0 * x0 + x2 * x2 + 1e-9f);
        float az  = atan2f(x2, x0) * (1.0f / PI_F);
        float el  = atan2f(x4, rxy) * (1.0f / PI_F);
        float rr  = sqrtf(x0 * x0 + x2 * x2 + x4 * x4 + 1e-9f);
        yp[p*9+0] = az; yp[p*9+1] = el; yp[p*9+2] = rr;
        yp[p*9+3] = az; yp[p*9+4] = el; yp[p*9+5] = 0.0f;
        yp[p*9+6] = az; yp[p*9+7] = 0.0f; yp[p*9+8] = 0.0f;
    }
    __half* A = g_ArnnH + r * 96;
#pragma unroll
    for (int m = 0; m < 27; m++) {
        float mv = meas[r * 27 + m];
        float mk = mask[r * 27 + m];
        float in = mv - yp[m];
        int mm = m % 9;
        bool ang = (mm == 0) | (mm == 1) | (mm == 3) | (mm == 4) | (mm == 6);
        if (ang) in = in - 2.0f * rintf(in * 0.5f);
        in *= mk;
        g_innov[r * 27 + m] = in;
        A[a16(m)]      = __float2half_rn(in);
        A[a16(27 + m)] = __float2half_rn(mk);
    }
    A[a16(54)] = __float2half_rn(dtv);
#pragma unroll
    for (int i = 0; i < 6; i++)  A[a16(55 + i)] = __float2half_rn(xm[i]);
#pragma unroll
    for (int i = 0; i < 12; i++) A[a16(61 + i)] = __float2half_rn(bl[i]);
#pragma unroll
    for (int i = 73; i < 96; i++) A[a16(i)] = __float2half_rn(0.0f);
}

// ================= K2: GRU (M=128/CTA, warps 2 rows x 4 cols) — unchanged from R9 =================
#define GSH 368
#define G_SMEM (128 * GSH * 2 + 4096)

__global__ __launch_bounds__(256, 1)
void gru_kernel(const float* __restrict__ hx, float* __restrict__ out_h) {
    extern __shared__ char smc[];
    __half* sAh   = (__half*)smc;
    float*  sBias = (float*)(smc + 128 * GSH * 2);
    const int tid = threadIdx.x, lane = tid & 31, wid = tid >> 5;
    const int wn = wid & 3, wm = wid >> 2;
    const int g = lane >> 2, tig = lane & 3;
    const int r0 = blockIdx.x * 128;

    for (int t = tid; t < 128 * 12; t += 256) {
        int row = t / 12, c = t % 12;
        ((uint4*)(sAh + row * GSH))[c] =
            ((const uint4*)(g_ArnnH + (size_t)(r0 + row) * 96))[c];
    }
    for (int t = tid; t < 128 * 64; t += 256) {
        int row = t >> 6, kq = (t & 63) << 2;
        float4 v = *(const float4*)(hx + (size_t)(r0 + row) * HID + kq);
        int base = row * GSH + 96 + ((kq >> 4) << 4) + perm16(kq & 15);
        *(uint32_t*)(sAh + base)     = pack2(v.x, v.y);
        *(uint32_t*)(sAh + base + 4) = pack2(v.z, v.w);
    }
    for (int t = tid; t < 1024; t += 256) sBias[t] = g_bias[t];
    __syncthreads();

    const int rowW = wm * 64 + g;

    for (int pass = 0; pass < 4; pass++) {
        const int jb  = pass * 64 + wn * 16;
        const int ntb = jb >> 3;
        float Cr[4][2][4], Cz[4][2][4], Cn[4][2][4], Ch[4][2][4];
#pragma unroll
        for (int mt = 0; mt < 4; mt++)
#pragma unroll
            for (int nt = 0; nt < 2; nt++)
#pragma unroll
                for (int e = 0; e < 4; e++) {
                    Cr[mt][nt][e] = 0.f; Cz[mt][nt][e] = 0.f;
                    Cn[mt][nt][e] = 0.f; Ch[mt][nt][e] = 0.f;
                }

        const uint32_t* BrP = g_WgU + WGU_R   + ntb * 1408 + lane * 4;
        const uint32_t* BzP = g_WgU + WGU_Z   + ntb * 1408 + lane * 4;
        const uint32_t* BiP = g_WgU + WGU_GIN + ntb * 384  + lane * 4;
        const uint32_t* BhP = g_WgU + WGU_GHN + ntb * 1024 + lane * 4;

        {
            uint4 br[2], bz[2];
#pragma unroll
            for (int nt = 0; nt < 2; nt++) {
                br[nt] = *(const uint4*)(BrP + nt * 1408);
                bz[nt] = *(const uint4*)(BzP + nt * 1408);
            }
            for (int ksp = 0; ksp < 11; ksp++) {
                const int jn = (ksp < 10) ? ksp + 1 : 10;
                uint4 brn[2], bzn[2];
#pragma unroll
                for (int nt = 0; nt < 2; nt++) {
                    brn[nt] = *(const uint4*)(BrP + nt * 1408 + jn * 128);
                    bzn[nt] = *(const uint4*)(BzP + nt * 1408 + jn * 128);
                }
                uint2 lo[2][4], hi[2][4];
#pragma unroll
                for (int sub = 0; sub < 2; sub++)
#pragma unroll
                    for (int mt = 0; mt < 4; mt++) {
                        const __half* ap = sAh + (rowW + mt * 16) * GSH
                                         + (ksp * 2 + sub) * 16 + tig * 4;
                        lo[sub][mt] = *(const uint2*)ap;
                        hi[sub][mt] = *(const uint2*)(ap + 8 * GSH);
                    }
#pragma unroll
                for (int nt = 0; nt < 2; nt++)
#pragma unroll
                    for (int mt = 0; mt < 4; mt++) {
                        mma16(Cr[mt][nt], lo[0][mt].x, hi[0][mt].x, lo[0][mt].y, hi[0][mt].y, br[nt].x, br[nt].y);
                        mma16(Cr[mt][nt], lo[1][mt].x, hi[1][mt].x, lo[1][mt].y, hi[1][mt].y, br[nt].z, br[nt].w);
                        mma16(Cz[mt][nt], lo[0][mt].x, hi[0][mt].x, lo[0][mt].y, hi[0][mt].y, bz[nt].x, bz[nt].y);
                        mma16(Cz[mt][nt], lo[1][mt].x, hi[1][mt].x, lo[1][mt].y, hi[1][mt].y, bz[nt].z, bz[nt].w);
                    }
#pragma unroll
                for (int nt = 0; nt < 2; nt++) { br[nt] = brn[nt]; bz[nt] = bzn[nt]; }
            }
        }
        {
            uint4 bi[2];
#pragma unroll
            for (int nt = 0; nt < 2; nt++) bi[nt] = *(const uint4*)(BiP + nt * 384);
            for (int ksp = 0; ksp < 3; ksp++) {
                const int jn = (ksp < 2) ? ksp + 1 : 2;
                uint4 bin[2];
#pragma unroll
                for (int nt = 0; nt < 2; nt++)
                    bin[nt] = *(const uint4*)(BiP + nt * 384 + jn * 128);
                uint2 lo[2][4], hi[2][4];
#pragma unroll
                for (int sub = 0; sub < 2; sub++)
#pragma unroll
                    for (int mt = 0; mt < 4; mt++) {
                        const __half* ap = sAh + (rowW + mt * 16) * GSH
                                         + (ksp * 2 + sub) * 16 + tig * 4;
                        lo[sub][mt] = *(const uint2*)ap;
                        hi[sub][mt] = *(const uint2*)(ap + 8 * GSH);
                    }
#pragma unroll
                for (int nt = 0; nt < 2; nt++)
#pragma unroll
                    for (int mt = 0; mt < 4; mt++) {
                        mma16(Cn[mt][nt], lo[0][mt].x, hi[0][mt].x, lo[0][mt].y, hi[0][mt].y, bi[nt].x, bi[nt].y);
                        mma16(Cn[mt][nt], lo[1][mt].x, hi[1][mt].x, lo[1][mt].y, hi[1][mt].y, bi[nt].z, bi[nt].w);
                    }
#pragma unroll
                for (int nt = 0; nt < 2; nt++) bi[nt] = bin[nt];
            }
        }
        {
            uint4 bh[2];
#pragma unroll
            for (int nt = 0; nt < 2; nt++) bh[nt] = *(const uint4*)(BhP + nt * 1024);
            for (int ksp = 0; ksp < 8; ksp++) {
                const int jn = (ksp < 7) ? ksp + 1 : 7;
                uint4 bhn[2];
#pragma unroll
                for (int nt = 0; nt < 2; nt++)
                    bhn[nt] = *(const uint4*)(BhP + nt * 1024 + jn * 128);
                uint2 lo[2][4], hi[2][4];
#pragma unroll
                for (int sub = 0; sub < 2; sub++)
#pragma unroll
                    for (int mt = 0; mt < 4; mt++) {
                        const __half* ap = sAh + (rowW + mt * 16) * GSH
                                         + (6 + ksp * 2 + sub) * 16 + tig * 4;
                        lo[sub][mt] = *(const uint2*)ap;
                        hi[sub][mt] = *(const uint2*)(ap + 8 * GSH);
                    }
#pragma unroll
                for (int nt = 0; nt < 2; nt++)
#pragma unroll
                    for (int mt = 0; mt < 4; mt++) {
                        mma16(Ch[mt][nt], lo[0][mt].x, hi[0][mt].x, lo[0][mt].y, hi[0][mt].y, bh[nt].x, bh[nt].y);
                        mma16(Ch[mt][nt], lo[1][mt].x, hi[1][mt].x, lo[1][mt].y, hi[1][mt].y, bh[nt].z, bh[nt].w);
                    }
#pragma unroll
                for (int nt = 0; nt < 2; nt++) bh[nt] = bhn[nt];
            }
        }
#pragma unroll
        for (int mt = 0; mt < 4; mt++)
#pragma unroll
            for (int nt = 0; nt < 2; nt++)
#pragma unroll
                for (int hh = 0; hh < 2; hh++) {
                    const int row = rowW + mt * 16 + hh * 8;
                    const int jc  = jb + nt * 8 + tig * 2;
                    float h2[2];
#pragma unroll
                    for (int e = 0; e < 2; e++) {
                        const int j = jc + e;
                        const int idx = hh * 2 + e;
                        float rg = sigm(Cr[mt][nt][idx] + sBias[j]);
                        float zg = sigm(Cz[mt][nt][idx] + sBias[256 + j]);
                        float nn = tanhf(Cn[mt][nt][idx] + sBias[512 + j]
                                         + rg * (Ch[mt][nt][idx] + sBias[768 + j]));
                        float hxv = __half2float(sAh[row * GSH + 96 + a16(j)]);
                        h2[e] = (1.0f - zg) * nn + zg * hxv;
                    }
                    *(float2*)(out_h + (size_t)(r0 + row) * HID + jc) = make_float2(h2[0], h2[1]);
                }
    }
}

// ================= K3: LN + MLP + gain head (M=64/CTA, 2 CTAs/SM, big tiles) =================
#define KS1 272
#define KS3 144
#define SKV 200
#define M_SMEM (64*KS1*2*2 + 64*KS3*2 + 64*28*4)  // 95232

__global__ __launch_bounds__(256, 2)
void mlp_kernel(const float* __restrict__ h_in,
                const float* __restrict__ ln_g, const float* __restrict__ ln_b,
                const float* __restrict__ b1, const float* __restrict__ b2,
                const float* __restrict__ b3, float* __restrict__ out_x) {
    extern __shared__ char smc[];
    __half* sA1h = (__half*)smc;                       // [64][KS1]
    __half* sA2h = sA1h + 64 * KS1;                    // [64][KS1]
    __half* sA3h = sA2h + 64 * KS1;                    // [64][KS3]
    float*  sInn = (float*)(smc + 64 * KS1 * 2 * 2 + 64 * KS3 * 2);  // [64][28]
    float*  sKV  = (float*)smc;                        // [64][SKV], overlays sA1h/sA2h
    const int tid = threadIdx.x, lane = tid & 31, wid = tid >> 5;
    const int g = lane >> 2, tig = lane & 3;
    const int r0 = blockIdx.x * 64;

    // stage h -> fp16 perm16
    for (int t = tid; t < 64 * 64; t += 256) {
        int row = t >> 6, kq = (t & 63) << 2;
        float4 v = *(const float4*)(h_in + (size_t)(r0 + row) * HID + kq);
        int base = row * KS1 + ((kq >> 4) << 4) + perm16(kq & 15);
        *(uint32_t*)(sA1h + base)     = pack2(v.x, v.y);
        *(uint32_t*)(sA1h + base + 4) = pack2(v.z, v.w);
    }
    for (int t = tid; t < 64 * 27; t += 256) {
        int row = t / 27, m = t % 27;
        sInn[row * 28 + m] = g_innov[(size_t)(r0 + row) * 27 + m];
    }
    __syncthreads();

    // LayerNorm on fp16 tile (stats in fp32)
    {
        const int row = tid >> 2, q = tid & 3;
        float s = 0.f, sq = 0.f;
        for (int i = 0; i < 64; i++) {
            float v = __half2float(sA1h[row * KS1 + q * 64 + i]);
            s += v; sq = fmaf(v, v, sq);
        }
        s  += __shfl_xor_sync(0xffffffffu, s, 1);  sq += __shfl_xor_sync(0xffffffffu, sq, 1);
        s  += __shfl_xor_sync(0xffffffffu, s, 2);  sq += __shfl_xor_sync(0xffffffffu, sq, 2);
        float mu = s * (1.0f / 256.0f);
        float var = sq * (1.0f / 256.0f) - mu * mu;
        float rs = rsqrtf(var + 1e-5f);
        for (int i = 0; i < 64; i++) {
            int p = q * 64 + i;
            int k = ((p >> 4) << 4) + invp16(p & 15);
            float v = __half2float(sA1h[row * KS1 + p]);
            sA1h[row * KS1 + p] =
                __float2half_rn((v - mu) * rs * __ldg(ln_g + k) + __ldg(ln_b + k));
        }
    }
    __syncthreads();

    // ---- MLP1: 1x8 layout, mt=4 (all 64 rows), nt=4 (32 cols/warp), ONE pass ----
    {
        float C[4][4][4];
#pragma unroll
        for (int mt = 0; mt < 4; mt++)
#pragma unroll
            for (int nt = 0; nt < 4; nt++)
#pragma unroll
                for (int e = 0; e < 4; e++) C[mt][nt][e] = 0.f;
        const uint32_t* BP = g_W1U + wid * 4096 + lane * 4;   // wid*4 ntiles, 1024/ntile
        for (int ksp = 0; ksp < 8; ksp++) {
            uint4 b[4];
#pragma unroll
            for (int nt = 0; nt < 4; nt++)
                b[nt] = *(const uint4*)(BP + nt * 1024 + ksp * 128);
#pragma unroll
            for (int mt = 0; mt < 4; mt++) {
                const __half* ap = sA1h + (g + mt * 16) * KS1 + ksp * 32 + tig * 4;
                uint2 lo0 = *(const uint2*)ap;
                uint2 hi0 = *(const uint2*)(ap + 8 * KS1);
                uint2 lo1 = *(const uint2*)(ap + 16);
                uint2 hi1 = *(const uint2*)(ap + 16 + 8 * KS1);
#pragma unroll
                for (int nt = 0; nt < 4; nt++) {
                    mma16(C[mt][nt], lo0.x, hi0.x, lo0.y, hi0.y, b[nt].x, b[nt].y);
                    mma16(C[mt][nt], lo1.x, hi1.x, lo1.y, hi1.y, b[nt].z, b[nt].w);
                }
            }
        }
#pragma unroll
        for (int mt = 0; mt < 4; mt++)
#pragma unroll
            for (int nt = 0; nt < 4; nt++)
#pragma unroll
                for (int hh = 0; hh < 2; hh++) {
                    const int row = g + mt * 16 + hh * 8;
                    const int j   = wid * 32 + nt * 8 + tig * 2;
                    float f0 = fmaxf(C[mt][nt][hh * 2 + 0] + __ldg(b1 + j),     0.0f);
                    float f1 = fmaxf(C[mt][nt][hh * 2 + 1] + __ldg(b1 + j + 1), 0.0f);
                    int pos = row * KS1 + ((j >> 4) << 4) + perm16(j & 15);
                    *(uint32_t*)(sA2h + pos) = pack2(f0, f1);
                }
    }
    __syncthreads();

    // ---- MLP2: 2x4 layout, mt=2 (32 rows), nt=4 (32 cols), ONE pass (N=128) ----
    {
        const int wm = wid >> 2, wn = wid & 3;
        const int rowW = wm * 32 + g;
        float C[2][4][4];
#pragma unroll
        for (int mt = 0; mt < 2; mt++)
#pragma unroll
            for (int nt = 0; nt < 4; nt++)
#pragma unroll
                for (int e = 0; e < 4; e++) C[mt][nt][e] = 0.f;
        const uint32_t* BP = g_W2U + wn * 4096 + lane * 4;
        for (int ksp = 0; ksp < 8; ksp++) {
            uint4 b[4];
#pragma unroll
            for (int nt = 0; nt < 4; nt++)
                b[nt] = *(const uint4*)(BP + nt * 1024 + ksp * 128);
#pragma unroll
            for (int mt = 0; mt < 2; mt++) {
                const __half* ap = sA2h + (rowW + mt * 16) * KS1 + ksp * 32 + tig * 4;
                uint2 lo0 = *(const uint2*)ap;
                uint2 hi0 = *(const uint2*)(ap + 8 * KS1);
                uint2 lo1 = *(const uint2*)(ap + 16);
                uint2 hi1 = *(const uint2*)(ap + 16 + 8 * KS1);
#pragma unroll
                for (int nt = 0; nt < 4; nt++) {
                    mma16(C[mt][nt], lo0.x, hi0.x, lo0.y, hi0.y, b[nt].x, b[nt].y);
                    mma16(C[mt][nt], lo1.x, hi1.x, lo1.y, hi1.y, b[nt].z, b[nt].w);
                }
            }
        }
#pragma unroll
        for (int mt = 0; mt < 2; mt++)
#pragma unroll
            for (int nt = 0; nt < 4; nt++)
#pragma unroll
                for (int hh = 0; hh < 2; hh++) {
                    const int row = rowW + mt * 16 + hh * 8;
                    const int j   = wn * 32 + nt * 8 + tig * 2;
                    float f0 = fmaxf(C[mt][nt][hh * 2 + 0] + __ldg(b2 + j),     0.0f);
                    float f1 = fmaxf(C[mt][nt][hh * 2 + 1] + __ldg(b2 + j + 1), 0.0f);
                    int pos = row * KS3 + ((j >> 4) << 4) + perm16(j & 15);
                    *(uint32_t*)(sA3h + pos) = pack2(f0, f1);
                }
    }
    __syncthreads();

    // ---- MLP3: 1x8 layout, mt=4, nt=3 (24 cols/warp), ONE pass (N=192) ----
    {
        float C[4][3][4];
#pragma unroll
        for (int mt = 0; mt < 4; mt++)
#pragma unroll
            for (int nt = 0; nt < 3; nt++)
#pragma unroll
                for (int e = 0; e < 4; e++) C[mt][nt][e] = 0.f;
        const uint32_t* BP = g_W3U + wid * 1536 + lane * 4;   // wid*3 ntiles, 512/ntile
        for (int ksp = 0; ksp < 4; ksp++) {
            uint4 b[3];
#pragma unroll
            for (int nt = 0; nt < 3; nt++)
                b[nt] = *(const uint4*)(BP + nt * 512 + ksp * 128);
#pragma unroll
            for (int mt = 0; mt < 4; mt++) {
                const __half* ap = sA3h + (g + mt * 16) * KS3 + ksp * 32 + tig * 4;
                uint2 lo0 = *(const uint2*)ap;
                uint2 hi0 = *(const uint2*)(ap + 8 * KS3);
                uint2 lo1 = *(const uint2*)(ap + 16);
                uint2 hi1 = *(const uint2*)(ap + 16 + 8 * KS3);
#pragma unroll
                for (int nt = 0; nt < 3; nt++) {
                    mma16(C[mt][nt], lo0.x, hi0.x, lo0.y, hi0.y, b[nt].x, b[nt].y);
                    mma16(C[mt][nt], lo1.x, hi1.x, lo1.y, hi1.y, b[nt].z, b[nt].w);
                }
            }
        }
#pragma unroll
        for (int mt = 0; mt < 4; mt++)
#pragma unroll
            for (int nt = 0; nt < 3; nt++)
#pragma unroll
                for (int hh = 0; hh < 2; hh++) {
                    const int row = g + mt * 16 + hh * 8;
                    const int j0  = wid * 24 + nt * 8 + tig * 2;
#pragma unroll
                    for (int e = 0; e < 2; e++) {
                        int j = j0 + e;
                        if (j < 162) {
                            float kv = C[mt][nt][hh * 2 + e] + __ldg(b3 + j);
                            sKV[row * SKV + j] = fminf(fmaxf(kv, -3.0f), 3.0f);
                        }
                    }
                }
    }
    __syncthreads();

    // ---- correction + clamp ----
    for (int t = tid; t < 384; t += 256) {
        const int row = t & 63, s = t >> 6;
        float corr = 0.f;
#pragma unroll
        for (int m = 0; m < 27; m++)
            corr = fmaf(sKV[row * SKV + s * 27 + m], sInn[row * 28 + m], corr);
        float xmv = g_xm[(size_t)(r0 + row) * 6 + s];
        out_x[(size_t)(r0 + row) * 6 + s] = fminf(fmaxf(xmv + corr, -5.0f), 5.0f);
    }
}

// ================= launch =================
extern "C" void kernel_launch(void* const* d_in, const int* in_sizes, int n_in,
                              void* d_out, int out_size)
{
    (void)in_sizes; (void)n_in; (void)out_size;
    const float* meas      = (const float*)d_in[0];
    const float* mask      = (const float*)d_in[1];
    const float* dtv       = (const float*)d_in[2];
    const float* baselines = (const float*)d_in[3];
    const float* x_prev    = (const float*)d_in[4];
    const float* hx        = (const float*)d_in[5];
    const float* W_ih      = (const float*)d_in[6];
    const float* W_hh      = (const float*)d_in[7];
    const float* b_ih      = (const float*)d_in[8];
    const float* b_hh      = (const float*)d_in[9];
    const float* ln_g      = (const float*)d_in[10];
    const float* ln_b      = (const float*)d_in[11];
    const float* W1        = (const float*)d_in[12];
    const float* b1        = (const float*)d_in[13];
    const float* W2        = (const float*)d_in[14];
    const float* b2        = (const float*)d_in[15];
    const float* W3        = (const float*)d_in[16];
    const float* b3        = (const float*)d_in[17];

    float* out   = (float*)d_out;
    float* out_x = out;                            // [B, 6]
    float* out_h = out + (size_t)B_TOTAL * 6;      // [B, 256]

    pack_kernel<<<(PACK_TOTAL + 255) / 256, 256>>>(W_ih, W_hh, b_ih, b_hh, W1, W2, W3);
    prep_kernel<<<B_TOTAL / 256, 256>>>(meas, mask, dtv, baselines, x_prev);

    cudaFuncSetAttribute(gru_kernel, cudaFuncAttributeMaxDynamicSharedMemorySize, G_SMEM);
    gru_kernel<<<B_TOTAL / 128, 256, G_SMEM>>>(hx, out_h);

    cudaFuncSetAttribute(mlp_kernel, cudaFuncAttributeMaxDynamicSharedMemorySize, M_SMEM);
    mlp_kernel<<<B_TOTAL / 64, 256, M_SMEM>>>(out_h, ln_g, ln_b, b1, b2, b3, out_x);
}